// round 14
// baseline (speedup 1.0000x reference)
#include <cuda_runtime.h>
#include <cuda_fp16.h>
#include <math.h>
#include <stdint.h>

// Problem dims (fixed by the dataset)
#define BB 4
#define SS 2048
#define DD 1024
#define HH 4096
#define MM (BB*SS)          // 8192 rows
#define NC 32               // scan chunks
#define CL (SS/NC)          // 64 steps per chunk
#define DD2 (DD/2)

// ---------------------------------------------------------------------------
// Scratch (static device globals; no allocation in kernel_launch)
// ---------------------------------------------------------------------------
__device__ __align__(16) float g_h1 [(size_t)MM*DD];    // h1 trunk (fp32)
__device__ __align__(16) float g_sa [(size_t)BB*NC*DD]; // chunk a-products
__device__ __align__(16) float g_sh [(size_t)BB*NC*DD]; // chunk h-carries

// fp16 streams
__device__ __align__(16) __half g_ah [(size_t)MM*DD];  // rmsnorm out / conv out / z
__device__ __align__(16) __half g_xbh[(size_t)MM*DD];  // xb (gemXY C1)
__device__ __align__(16) __half g_ybh[(size_t)MM*DD];  // yb (gemXY C2, gelu)
__device__ __align__(16) __half g_rl [(size_t)MM*DD];  // rlin -> a (in place)
__device__ __align__(16) __half g_il [(size_t)MM*DD];  // ilin
__device__ __align__(16) __half g_lh [(size_t)MM*DD];  // scan local h (fp16)
__device__ __align__(16) __half g_zh [(size_t)MM*HH];  // gated-MLP intermediate
// fp16 transposed weights, packed arena (17M halfs)
#define WOFF_X  ((size_t)0)
#define WOFF_Y  ((size_t)1*1024*1024)   // follows X (dual Wx|Wy)
#define WOFF_A  ((size_t)2*1024*1024)
#define WOFF_I  ((size_t)3*1024*1024)   // follows A (dual Wa|Wi)
#define WOFF_O  ((size_t)4*1024*1024)
#define WOFF_GU ((size_t)5*1024*1024)   // Wg/Wu column-interleaved (8192 rows)
#define WOFF_D  ((size_t)13*1024*1024)
__device__ __align__(16) __half g_wh[(size_t)17*1024*1024];

// ---------------------------------------------------------------------------
// Math helpers
// ---------------------------------------------------------------------------
__device__ __forceinline__ float geluf(float x) {
    const float c = 0.7978845608028654f; // sqrt(2/pi)
    float x3 = x * x * x;
    float t  = tanhf(c * (x + 0.044715f * x3));
    return 0.5f * x * (1.0f + t);
}
__device__ __forceinline__ float sigmoidf(float x) {
    return 1.0f / (1.0f + expf(-x));
}
__device__ __forceinline__ float softplusf(float x) {
    return fmaxf(x, 0.0f) + log1pf(expf(-fabsf(x)));
}

// ---------------------------------------------------------------------------
// PTX helpers (baseline compute_103 features only)
// ---------------------------------------------------------------------------
__device__ __forceinline__ uint32_t smem_u32(const void* p) {
    uint32_t a;
    asm("{ .reg .u64 t; cvta.to.shared.u64 t, %1; cvt.u32.u64 %0, t; }" : "=r"(a) : "l"(p));
    return a;
}
__device__ __forceinline__ void cp_async16(uint32_t dst, const void* src) {
    asm volatile("cp.async.cg.shared.global [%0], [%1], 16;" :: "r"(dst), "l"(src) : "memory");
}
__device__ __forceinline__ void ldm_x4(uint32_t& r0, uint32_t& r1, uint32_t& r2, uint32_t& r3,
                                       uint32_t addr) {
    asm volatile("ldmatrix.sync.aligned.m8n8.x4.shared.b16 {%0,%1,%2,%3}, [%4];"
                 : "=r"(r0), "=r"(r1), "=r"(r2), "=r"(r3) : "r"(addr));
}
__device__ __forceinline__ void mma16816(float* c, const uint32_t* a, const uint32_t* b) {
    asm volatile(
        "mma.sync.aligned.m16n8k16.row.col.f32.f16.f16.f32 "
        "{%0,%1,%2,%3}, {%4,%5,%6,%7}, {%8,%9}, {%0,%1,%2,%3};"
        : "+f"(c[0]), "+f"(c[1]), "+f"(c[2]), "+f"(c[3])
        : "r"(a[0]), "r"(a[1]), "r"(a[2]), "r"(a[3]), "r"(b[0]), "r"(b[1]));
}

// ---------------------------------------------------------------------------
// Single-product fp16 HMMA GEMM: C = act(A @ W^T) (+R).
// CTA 256x128, BK=64, 8 warps (4M x 2N, warp tile 64x64), 4-stage cp.async,
// fill-distance 3, single __syncthreads per chunk, 1 CTA/SM, 256 threads.
// Warp tile 64x64 cuts ldmatrix SMEM reads 33% vs 64x32 (same HMMA count).
// ---------------------------------------------------------------------------
#define GSTRIDE 144u
#define TILE_A  36864u            // 256 rows * 144B
#define STG_B   55296u            // A(36864) + B(18432)
#define GEMM_SMEM (4*STG_B)       // 221184

template<int ACT1, int ACT2, bool RES, bool GATED, bool OUT16>
__global__ void __launch_bounds__(256, 1)
hmma_gemm(const __half* __restrict__ Ah, const __half* __restrict__ Bh,
          const float* __restrict__ R, float* __restrict__ C1, float* __restrict__ C2,
          __half* __restrict__ H1o, __half* __restrict__ H2o,
          __half* __restrict__ ZH,
          int NH, int K)
{
    extern __shared__ char smem[];
    const uint32_t sb = smem_u32(smem);
    const int tid  = threadIdx.x;
    const int wid  = tid >> 5;
    const int lane = tid & 31;
    const int bm = blockIdx.y * 256;
    const int bn = blockIdx.x * 128;
    const int wr = wid >> 1;          // warp row 0..3 (64 rows each)
    const int wc = wid & 1;           // warp col 0..1 (64 cols each)

    const int nch = K >> 6;           // BK = 64

    auto fill = [&](int ch) {
        const int k0 = ch << 6;
        const uint32_t st = sb + (uint32_t)(ch & 3) * STG_B;
        #pragma unroll
        for (int r = 0; r < 8; r++) {            // A: 2048 16B chunks
            const int c = tid + (r << 8);
            const int row = c >> 3, kc = c & 7;
            const uint32_t dst = (uint32_t)row * GSTRIDE + (uint32_t)(kc << 4);
            cp_async16(st + dst, Ah + (size_t)(bm + row) * K + k0 + (kc << 3));
        }
        #pragma unroll
        for (int r = 0; r < 4; r++) {            // B: 1024 16B chunks
            const int c = tid + (r << 8);
            const int row = c >> 3, kc = c & 7;
            const uint32_t dst = (uint32_t)row * GSTRIDE + (uint32_t)(kc << 4);
            cp_async16(st + TILE_A + dst, Bh + (size_t)(bn + row) * K + k0 + (kc << 3));
        }
        asm volatile("cp.async.commit_group;" ::: "memory");
    };

    float acc[4][8][4];
    #pragma unroll
    for (int i = 0; i < 4; i++)
        #pragma unroll
        for (int j = 0; j < 8; j++)
            #pragma unroll
            for (int q = 0; q < 4; q++) acc[i][j][q] = 0.0f;

    fill(0);
    if (nch > 1) fill(1);
    if (nch > 2) fill(2);

    const int l16  = lane & 15;
    const int ahi  = (lane >> 4) << 4;
    const int brow = ((lane >> 4) << 3) + (lane & 7);
    const int bhi  = ((lane >> 3) & 1) << 4;

    for (int i = 0; i < nch; i++) {
        if      (i + 2 < nch) asm volatile("cp.async.wait_group 2;" ::: "memory");
        else if (i + 1 < nch) asm volatile("cp.async.wait_group 1;" ::: "memory");
        else                  asm volatile("cp.async.wait_group 0;" ::: "memory");
        __syncthreads();   // single barrier per chunk (fill-distance-3, 4 buffers)

        const uint32_t st  = sb + (uint32_t)(i & 3) * STG_B;
        const uint32_t sAh = st;
        const uint32_t sBh = st + TILE_A;

        #pragma unroll
        for (int ks = 0; ks < 4; ks++) {
            uint32_t ah[4][4];
            #pragma unroll
            for (int mt = 0; mt < 4; mt++) {
                const uint32_t ra = (uint32_t)(wr*64 + mt*16 + l16) * GSTRIDE
                                  + (uint32_t)(ks*32 + ahi);
                ldm_x4(ah[mt][0], ah[mt][1], ah[mt][2], ah[mt][3], sAh + ra);
            }
            #pragma unroll
            for (int ntp = 0; ntp < 4; ntp++) {
                uint32_t bq[4];
                const uint32_t rb = (uint32_t)(wc*64 + ntp*16 + brow) * GSTRIDE
                                  + (uint32_t)(ks*32 + bhi);
                ldm_x4(bq[0], bq[1], bq[2], bq[3], sBh + rb);
                #pragma unroll
                for (int mt = 0; mt < 4; mt++) {
                    mma16816(acc[mt][2*ntp],   ah[mt], bq);
                    mma16816(acc[mt][2*ntp+1], ah[mt], bq + 2);
                }
            }
        }
        if (i + 3 < nch) fill(i + 3);
    }

    const int erow = lane >> 2;
    const int ecol = (lane & 3) << 1;

    if constexpr (GATED) {
        #pragma unroll
        for (int mt = 0; mt < 4; mt++) {
            #pragma unroll
            for (int nt = 0; nt < 8; nt++) {
                const int r0 = bm + wr*64 + mt*16 + erow;
                const int j  = ((bn + wc*64 + nt*8 + ecol) >> 1);
                const float f0 = geluf(acc[mt][nt][0]) * acc[mt][nt][1];
                const float f1 = geluf(acc[mt][nt][2]) * acc[mt][nt][3];
                const float f0n = __shfl_down_sync(0xffffffff, f0, 1);
                const float f1n = __shfl_down_sync(0xffffffff, f1, 1);
                if ((lane & 1) == 0) {
                    *(__half2*)(ZH + (size_t)r0     * NH + j) = __floats2half2_rn(f0, f0n);
                    *(__half2*)(ZH + (size_t)(r0+8) * NH + j) = __floats2half2_rn(f1, f1n);
                }
            }
        }
        return;
    }

    if constexpr (OUT16) {
        __half* Hout;
        int act, cb;
        if (bn < NH) { Hout = H1o; act = ACT1; cb = bn; }
        else         { Hout = H2o; act = ACT2; cb = bn - NH; }
        #pragma unroll
        for (int mt = 0; mt < 4; mt++) {
            #pragma unroll
            for (int nt = 0; nt < 8; nt++) {
                const int r0 = bm + wr*64 + mt*16 + erow;
                const int cc = cb + wc*64 + nt*8 + ecol;
                float v0 = acc[mt][nt][0], v1 = acc[mt][nt][1];
                float v2 = acc[mt][nt][2], v3 = acc[mt][nt][3];
                if (act == 1) { v0 = geluf(v0); v1 = geluf(v1); v2 = geluf(v2); v3 = geluf(v3); }
                *(__half2*)(Hout + (size_t)r0     * NH + cc) =
                    __floats2half2_rn(v0, v1);
                *(__half2*)(Hout + (size_t)(r0+8) * NH + cc) =
                    __floats2half2_rn(v2, v3);
            }
        }
        return;
    }

    // fp32 epilogue (with residual)
    float* Cout;
    int act, cb;
    if (bn < NH) { Cout = C1; act = ACT1; cb = bn; }
    else         { Cout = C2; act = ACT2; cb = bn - NH; }

    #pragma unroll
    for (int mt = 0; mt < 4; mt++) {
        #pragma unroll
        for (int nt = 0; nt < 8; nt++) {
            const int r0 = bm + wr*64 + mt*16 + erow;
            const int cc = cb + wc*64 + nt*8 + ecol;
            float v0 = acc[mt][nt][0], v1 = acc[mt][nt][1];
            float v2 = acc[mt][nt][2], v3 = acc[mt][nt][3];
            if (act == 1) { v0 = geluf(v0); v1 = geluf(v1); v2 = geluf(v2); v3 = geluf(v3); }
            if (RES) {
                const float2 ra = *(const float2*)(R + (size_t)r0 * NH + cc);
                const float2 rb = *(const float2*)(R + (size_t)(r0+8) * NH + cc);
                v0 += ra.x; v1 += ra.y; v2 += rb.x; v3 += rb.y;
            }
            *(float2*)(Cout + (size_t)r0     * NH + cc) = make_float2(v0, v1);
            *(float2*)(Cout + (size_t)(r0+8) * NH + cc) = make_float2(v2, v3);
        }
    }
}

// ---------------------------------------------------------------------------
// Weight transpose to fp16 with half2-vectorized stores.
// Single fused kernel: flattened grid over all 8 transposes.
// ---------------------------------------------------------------------------
__device__ __forceinline__ void tsplit_body(const float* __restrict__ W,
                                            __half* __restrict__ Th,
                                            int Kd, int Nd, int rstride, int roff,
                                            int bx, int by)
{
    __shared__ float tile[32][33];   // [k_local][n_local]
    const int n0 = bx * 32, k0 = by * 32;
    const int tx = threadIdx.x, ty = threadIdx.y;   // (32, 8)
    #pragma unroll
    for (int i = 0; i < 32; i += 8)
        tile[ty + i][tx] = W[(size_t)(k0 + ty + i) * Nd + n0 + tx];
    __syncthreads();
    const int j  = tx & 15;
    const int nn = ty + ((tx >> 4) << 3);
    #pragma unroll
    for (int i = 0; i < 32; i += 16) {
        const float v0 = tile[2*j][nn + i];
        const float v1 = tile[2*j + 1][nn + i];
        const size_t o = ((size_t)(n0 + nn + i) * rstride + roff) * Kd + k0 + 2*j;
        *(__half2*)&Th[o] = __floats2half2_rn(v0, v1);
    }
}

__global__ void prep_all_kernel(const float* __restrict__ Wx, const float* __restrict__ Wy,
                                const float* __restrict__ Wa, const float* __restrict__ Wi,
                                const float* __restrict__ Wo, const float* __restrict__ Wg,
                                const float* __restrict__ Wu, const float* __restrict__ Wd,
                                __half* __restrict__ wh)
{
    int b = blockIdx.x;
    if (b < 5 * 1024) {
        const int w = b >> 10;
        const int t = b & 1023;
        const float* W;
        size_t off;
        switch (w) {
            case 0:  W = Wx; off = WOFF_X; break;
            case 1:  W = Wy; off = WOFF_Y; break;
            case 2:  W = Wa; off = WOFF_A; break;
            case 3:  W = Wi; off = WOFF_I; break;
            default: W = Wo; off = WOFF_O; break;
        }
        tsplit_body(W, wh + off, DD, DD, 1, 0, t & 31, t >> 5);
        return;
    }
    b -= 5 * 1024;
    if (b < 4096) {        // Wg: even interleaved rows
        tsplit_body(Wg, wh + WOFF_GU, DD, HH, 2, 0, b & 127, b >> 7);
        return;
    }
    b -= 4096;
    if (b < 4096) {        // Wu: odd interleaved rows
        tsplit_body(Wu, wh + WOFF_GU, DD, HH, 2, 1, b & 127, b >> 7);
        return;
    }
    b -= 4096;             // Wd
    tsplit_body(Wd, wh + WOFF_D, HH, DD, 1, 0, b & 31, b >> 5);
}

// ---------------------------------------------------------------------------
// RMSNorm with fp16 output (float2 / half2 vectorized; D=1024, 256 threads)
// ---------------------------------------------------------------------------
__global__ void rmsnorm_f16_kernel(const float* __restrict__ x,
                                   const float* __restrict__ w,
                                   __half* __restrict__ oh)
{
    const int row = blockIdx.x;
    const float2* xr = (const float2*)(x + (size_t)row * DD);
    const float2* w2 = (const float2*)w;
    float ss = 0.0f;
    float2 v[2];
    #pragma unroll
    for (int r = 0; r < 2; r++) {
        v[r] = xr[threadIdx.x + r * 256];
        ss = fmaf(v[r].x, v[r].x, fmaf(v[r].y, v[r].y, ss));
    }
    #pragma unroll
    for (int off = 16; off > 0; off >>= 1)
        ss += __shfl_xor_sync(0xffffffff, ss, off);
    __shared__ float red[8];
    const int lane = threadIdx.x & 31, wid = threadIdx.x >> 5;
    if (lane == 0) red[wid] = ss;
    __syncthreads();
    if (wid == 0) {
        float s = (lane < 8) ? red[lane] : 0.0f;
        #pragma unroll
        for (int off = 4; off > 0; off >>= 1)
            s += __shfl_xor_sync(0xffffffff, s, off);
        if (lane == 0) red[0] = s;
    }
    __syncthreads();
    const float inv = rsqrtf(red[0] / (float)DD + 1e-6f);
    __half2* o2 = (__half2*)(oh + (size_t)row * DD);
    #pragma unroll
    for (int r = 0; r < 2; r++) {
        const float2 ww = w2[threadIdx.x + r * 256];
        o2[threadIdx.x + r * 256] =
            __floats2half2_rn(v[r].x * inv * ww.x, v[r].y * inv * ww.y);
    }
}

// ---------------------------------------------------------------------------
// Causal depthwise conv (K=4), half2 vectorized, 4 sequence positions/thread.
// ---------------------------------------------------------------------------
#define S4 (SS/4)
__global__ void conv_f16_kernel(const __half2* __restrict__ in,
                                const float* __restrict__ cw,
                                const float* __restrict__ cb,
                                __half2* __restrict__ oh)
{
    const int idx = blockIdx.x * blockDim.x + threadIdx.x;
    if (idx >= BB * S4 * DD2) return;
    const int d2    = idx % DD2;
    const int s4    = (idx / DD2) % S4;
    const int batch = idx / (DD2 * S4);
    const int s0    = s4 * 4;
    const size_t base = ((size_t)batch * SS + s0) * DD2 + d2;

    float2 v[7];
    #pragma unroll
    for (int i = 0; i < 7; i++) {
        const int s = s0 + i - 3;
        v[i] = (s >= 0) ? __half22float2(in[base + (size_t)(i - 3) * DD2])
                        : make_float2(0.0f, 0.0f);
    }
    float w0[4], w1[4];
    #pragma unroll
    for (int k = 0; k < 4; k++) {
        w0[k] = cw[k * DD + 2*d2];
        w1[k] = cw[k * DD + 2*d2 + 1];
    }
    const float b0 = cb[2*d2], b1 = cb[2*d2 + 1];

    #pragma unroll
    for (int j = 0; j < 4; j++) {
        float a0 = b0, a1 = b1;
        #pragma unroll
        for (int k = 0; k < 4; k++) {
            a0 = fmaf(w0[k], v[j + k].x, a0);
            a1 = fmaf(w1[k], v[j + k].y, a1);
        }
        oh[base + (size_t)j * DD2] = __floats2half2_rn(a0, a1);
    }
}

// ---------------------------------------------------------------------------
// Scan pass 1 (half2): gates + chunk-local scan.
// ---------------------------------------------------------------------------
__global__ void scan1_kernel(__half2* __restrict__ rlin_a,
                             const __half2* __restrict__ ilin,
                             const __half2* __restrict__ xc,
                             const float* __restrict__ lam,
                             __half2* __restrict__ lh,
                             float2* __restrict__ sa,
                             float2* __restrict__ sh)
{
    const int idx = blockIdx.x * blockDim.x + threadIdx.x;
    if (idx >= BB * NC * DD2) return;
    const int d2    = idx % DD2;
    const int chunk = (idx / DD2) % NC;
    const int batch = idx / (DD2 * NC);
    const float cf0 = -8.0f * softplusf(lam[2*d2]);
    const float cf1 = -8.0f * softplusf(lam[2*d2 + 1]);
    const size_t base = ((size_t)batch * SS + (size_t)chunk * CL) * DD2 + d2;

    float p0 = 1.0f, p1 = 1.0f, h0 = 0.0f, h1 = 0.0f;
    for (int t = 0; t < CL; t++) {
        const size_t off = base + (size_t)t * DD2;
        const float2 rv = __half22float2(rlin_a[off]);
        const float2 iv = __half22float2(ilin[off]);
        const float2 xv = __half22float2(xc[off]);
        const float a0 = expf(cf0 * sigmoidf(rv.x));
        const float a1 = expf(cf1 * sigmoidf(rv.y));
        const float b0 = sqrtf(fmaxf(1.0f - a0*a0, 1e-12f)) * sigmoidf(iv.x) * xv.x;
        const float b1 = sqrtf(fmaxf(1.0f - a1*a1, 1e-12f)) * sigmoidf(iv.y) * xv.y;
        h0 = fmaf(a0, h0, b0);
        h1 = fmaf(a1, h1, b1);
        p0 *= a0; p1 *= a1;
        rlin_a[off] = __floats2half2_rn(a0, a1);
        lh[off]     = __floats2half2_rn(h0, h1);
    }
    sa[idx] = make_float2(p0, p1);
    sh[idx] = make_float2(h0, h1);
}

// ---------------------------------------------------------------------------
// Scan pass 2 (float2): combine chunk carries.
// ---------------------------------------------------------------------------
__global__ void scan2_kernel(const float2* __restrict__ sa, float2* __restrict__ sh)
{
    const int idx = blockIdx.x * blockDim.x + threadIdx.x;
    if (idx >= BB * DD2) return;
    const int d2 = idx % DD2, batch = idx / DD2;
    float H0 = 0.0f, H1 = 0.0f;
    for (int c = 0; c < NC; c++) {
        const size_t o = ((size_t)batch * NC + c) * DD2 + d2;
        const float2 av = sa[o];
        const float2 hv = sh[o];
        H0 = fmaf(av.x, H0, hv.x);
        H1 = fmaf(av.y, H1, hv.y);
        sh[o] = make_float2(H0, H1);
    }
}

// ---------------------------------------------------------------------------
// Scan pass 3 (half2): apply carries, z = h * yb, fp16 out.
// ---------------------------------------------------------------------------
__global__ void scan3_kernel(const __half2* __restrict__ aArr,
                             const __half2* __restrict__ lhArr,
                             const float2* __restrict__ sh,
                             const __half2* __restrict__ yb,
                             __half2* __restrict__ zh)
{
    const int idx = blockIdx.x * blockDim.x + threadIdx.x;
    if (idx >= BB * NC * DD2) return;
    const int d2    = idx % DD2;
    const int chunk = (idx / DD2) % NC;
    const int batch = idx / (DD2 * NC);
    float c0 = 0.0f, c1 = 0.0f;
    if (chunk != 0) {
        const float2 cv = sh[((size_t)batch * NC + chunk - 1) * DD2 + d2];
        c0 = cv.x; c1 = cv.y;
    }
    const size_t base = ((size_t)batch * SS + (size_t)chunk * CL) * DD2 + d2;

    float p0 = 1.0f, p1 = 1.0f;
    for (int t = 0; t < CL; t++) {
        const size_t off = base + (size_t)t * DD2;
        const float2 av = __half22float2(aArr[off]);
        const float2 lv = __half22float2(lhArr[off]);
        const float2 yv = __half22float2(yb[off]);
        p0 *= av.x; p1 *= av.y;
        const float z0 = fmaf(p0, c0, lv.x) * yv.x;
        const float z1 = fmaf(p1, c1, lv.y) * yv.y;
        zh[off] = __floats2half2_rn(z0, z1);
    }
}

// ---------------------------------------------------------------------------
// Launch
// ---------------------------------------------------------------------------
extern "C" void kernel_launch(void* const* d_in, const int* in_sizes, int n_in,
                              void* d_out, int out_size)
{
    const float* x       = (const float*)d_in[0];
    const float* norm1_w = (const float*)d_in[1];
    const float* Wx      = (const float*)d_in[2];
    const float* Wy      = (const float*)d_in[3];
    const float* conv_w  = (const float*)d_in[4];
    const float* conv_b  = (const float*)d_in[5];
    const float* Wi      = (const float*)d_in[6];
    const float* Wa      = (const float*)d_in[7];
    const float* lam     = (const float*)d_in[8];
    const float* Wo      = (const float*)d_in[9];
    const float* norm2_w = (const float*)d_in[10];
    const float* Wg      = (const float*)d_in[11];
    const float* Wu      = (const float*)d_in[12];
    const float* Wd      = (const float*)d_in[13];
    float* out = (float*)d_out;

    float *h1, *sa, *sh;
    __half *ah, *xbh, *ybh, *rl, *il, *lh, *zh, *wh;
    cudaGetSymbolAddress((void**)&h1,  g_h1);
    cudaGetSymbolAddress((void**)&sa,  g_sa);
    cudaGetSymbolAddress((void**)&sh,  g_sh);
    cudaGetSymbolAddress((void**)&ah,  g_ah);
    cudaGetSymbolAddress((void**)&xbh, g_xbh);
    cudaGetSymbolAddress((void**)&ybh, g_ybh);
    cudaGetSymbolAddress((void**)&rl,  g_rl);
    cudaGetSymbolAddress((void**)&il,  g_il);
    cudaGetSymbolAddress((void**)&lh,  g_lh);
    cudaGetSymbolAddress((void**)&zh,  g_zh);
    cudaGetSymbolAddress((void**)&wh,  g_wh);

    cudaFuncSetAttribute(hmma_gemm<0,1,false,false,true>,  cudaFuncAttributeMaxDynamicSharedMemorySize, GEMM_SMEM);
    cudaFuncSetAttribute(hmma_gemm<0,0,false,false,true>,  cudaFuncAttributeMaxDynamicSharedMemorySize, GEMM_SMEM);
    cudaFuncSetAttribute(hmma_gemm<0,0,true,false,false>,  cudaFuncAttributeMaxDynamicSharedMemorySize, GEMM_SMEM);
    cudaFuncSetAttribute(hmma_gemm<0,0,false,true,false>,  cudaFuncAttributeMaxDynamicSharedMemorySize, GEMM_SMEM);

    const dim3 tsb(32, 8);
    const int gCV = (BB * S4 * DD2 + 255) / 256;     // conv: 4 s-positions/thread
    const int gSC2 = (BB * NC * DD2 + 255) / 256;

    const dim3 gemXY(2048 / 128, MM / 256);   // dual Wx|Wy (fp16 out)
    const dim3 gemAI(2048 / 128, MM / 256);   // dual Wa|Wi (fp16 out)
    const dim3 gemGU(8192 / 128, MM / 256);   // interleaved Wg|Wu (gated)
    const dim3 gemO (1024 / 128, MM / 256);   // Wo (K=1024, fp32+res)
    const dim3 gemDn(1024 / 128, MM / 256);   // Wd (K=4096, fp32+res)

    // all weight prep in ONE launch + rmsnorm1
    prep_all_kernel<<<5*1024 + 3*4096, tsb>>>(Wx, Wy, Wa, Wi, Wo, Wg, Wu, Wd, wh);
    rmsnorm_f16_kernel<<<MM, 256>>>(x, norm1_w, ah);
    // xb = t @ Wx ; yb = gelu(t @ Wy)  [dual, fp16 out]
    hmma_gemm<0,1,false,false,true><<<gemXY, 256, GEMM_SMEM>>>(ah, wh + WOFF_X,
        nullptr, nullptr, nullptr, xbh, ybh, nullptr, DD, DD);
    // conv -> ah (fp16)
    conv_f16_kernel<<<gCV, 256>>>((const __half2*)xbh, conv_w, conv_b, (__half2*)ah);
    // rlin -> rl ; ilin -> il  [dual, fp16 out]
    hmma_gemm<0,0,false,false,true><<<gemAI, 256, GEMM_SMEM>>>(ah, wh + WOFF_A,
        nullptr, nullptr, nullptr, rl, il, nullptr, DD, DD);
    // gates + chunked scan + z = h*yb -> ah (fp16)
    scan1_kernel<<<gSC2, 256>>>((__half2*)rl, (const __half2*)il, (const __half2*)ah,
                                lam, (__half2*)lh, (float2*)sa, (float2*)sh);
    scan2_kernel<<<(BB * DD2 + 255) / 256, 256>>>((const float2*)sa, (float2*)sh);
    scan3_kernel<<<gSC2, 256>>>((const __half2*)rl, (const __half2*)lh,
                                (const float2*)sh, (const __half2*)ybh, (__half2*)ah);
    // h1 = x + z @ Wo
    hmma_gemm<0,0,true,false,false><<<gemO, 256, GEMM_SMEM>>>(ah, wh + WOFF_O,
        x, h1, h1, nullptr, nullptr, nullptr, DD, DD);
    // u = rmsnorm(h1) -> ah
    rmsnorm_f16_kernel<<<MM, 256>>>(h1, norm2_w, ah);
    // ff = gelu(u @ Wg) * (u @ Wu) -> zh  [gated]
    hmma_gemm<0,0,false,true,false><<<gemGU, 256, GEMM_SMEM>>>(ah, wh + WOFF_GU,
        nullptr, nullptr, nullptr, nullptr, nullptr, zh, HH, DD);
    // out = h1 + ff @ Wd
    hmma_gemm<0,0,true,false,false><<<gemDn, 256, GEMM_SMEM>>>(zh, wh + WOFF_D,
        h1, out, out, nullptr, nullptr, nullptr, DD, HH);
}

// round 15
// speedup vs baseline: 1.0015x; 1.0015x over previous
#include <cuda_runtime.h>
#include <cuda_fp16.h>
#include <math.h>
#include <stdint.h>

// Problem dims (fixed by the dataset)
#define BB 4
#define SS 2048
#define DD 1024
#define HH 4096
#define MM (BB*SS)          // 8192 rows
#define NC 32               // scan chunks
#define CL (SS/NC)          // 64 steps per chunk
#define DD2 (DD/2)

// ---------------------------------------------------------------------------
// Scratch (static device globals; no allocation in kernel_launch)
// ---------------------------------------------------------------------------
__device__ __align__(16) float g_sa [(size_t)BB*NC*DD]; // chunk a-products
__device__ __align__(16) float g_sh [(size_t)BB*NC*DD]; // chunk h-carries

// fp16 streams
__device__ __align__(16) __half g_ah [(size_t)MM*DD];  // rmsnorm out / conv out / z
__device__ __align__(16) __half g_xbh[(size_t)MM*DD];  // xb (gemXY C1) -> later h1 (fp16)
__device__ __align__(16) __half g_ybh[(size_t)MM*DD];  // yb (gemXY C2, gelu)
__device__ __align__(16) __half g_rl [(size_t)MM*DD];  // rlin -> a (in place)
__device__ __align__(16) __half g_il [(size_t)MM*DD];  // ilin
__device__ __align__(16) __half g_lh [(size_t)MM*DD];  // scan local h (fp16)
__device__ __align__(16) __half g_zh [(size_t)MM*HH];  // gated-MLP intermediate
// fp16 transposed weights, packed arena (17M halfs)
#define WOFF_X  ((size_t)0)
#define WOFF_Y  ((size_t)1*1024*1024)   // follows X (dual Wx|Wy)
#define WOFF_A  ((size_t)2*1024*1024)
#define WOFF_I  ((size_t)3*1024*1024)   // follows A (dual Wa|Wi)
#define WOFF_O  ((size_t)4*1024*1024)
#define WOFF_GU ((size_t)5*1024*1024)   // Wg/Wu column-interleaved (8192 rows)
#define WOFF_D  ((size_t)13*1024*1024)
__device__ __align__(16) __half g_wh[(size_t)17*1024*1024];

// ---------------------------------------------------------------------------
// Math helpers
// ---------------------------------------------------------------------------
__device__ __forceinline__ float geluf(float x) {
    const float c = 0.7978845608028654f; // sqrt(2/pi)
    float x3 = x * x * x;
    float t  = tanhf(c * (x + 0.044715f * x3));
    return 0.5f * x * (1.0f + t);
}
__device__ __forceinline__ float sigmoidf(float x) {
    return 1.0f / (1.0f + expf(-x));
}
__device__ __forceinline__ float softplusf(float x) {
    return fmaxf(x, 0.0f) + log1pf(expf(-fabsf(x)));
}

// ---------------------------------------------------------------------------
// PTX helpers (baseline compute_103 features only)
// ---------------------------------------------------------------------------
__device__ __forceinline__ uint32_t smem_u32(const void* p) {
    uint32_t a;
    asm("{ .reg .u64 t; cvta.to.shared.u64 t, %1; cvt.u32.u64 %0, t; }" : "=r"(a) : "l"(p));
    return a;
}
__device__ __forceinline__ void cp_async16(uint32_t dst, const void* src) {
    asm volatile("cp.async.cg.shared.global [%0], [%1], 16;" :: "r"(dst), "l"(src) : "memory");
}
__device__ __forceinline__ void ldm_x4(uint32_t& r0, uint32_t& r1, uint32_t& r2, uint32_t& r3,
                                       uint32_t addr) {
    asm volatile("ldmatrix.sync.aligned.m8n8.x4.shared.b16 {%0,%1,%2,%3}, [%4];"
                 : "=r"(r0), "=r"(r1), "=r"(r2), "=r"(r3) : "r"(addr));
}
__device__ __forceinline__ void mma16816(float* c, const uint32_t* a, const uint32_t* b) {
    asm volatile(
        "mma.sync.aligned.m16n8k16.row.col.f32.f16.f16.f32 "
        "{%0,%1,%2,%3}, {%4,%5,%6,%7}, {%8,%9}, {%0,%1,%2,%3};"
        : "+f"(c[0]), "+f"(c[1]), "+f"(c[2]), "+f"(c[3])
        : "r"(a[0]), "r"(a[1]), "r"(a[2]), "r"(a[3]), "r"(b[0]), "r"(b[1]));
}

// ---------------------------------------------------------------------------
// Single-product fp16 HMMA GEMM: C = act(A @ W^T) (+R fp32 / +RH fp16).
// CTA 256x128, BK=64, 16 warps (4Mx4N, warp tile 64x32), 4-stage cp.async,
// fill-distance 3, single __syncthreads per chunk, 1 CTA/SM  (R13 config).
// ---------------------------------------------------------------------------
#define GSTRIDE 144u
#define TILE_A  36864u            // 256 rows * 144B
#define STG_B   55296u            // A(36864) + B(18432)
#define GEMM_SMEM (4*STG_B)       // 221184

template<int ACT1, int ACT2, bool RES, bool RESH, bool GATED, bool OUT16>
__global__ void __launch_bounds__(512, 1)
hmma_gemm(const __half* __restrict__ Ah, const __half* __restrict__ Bh,
          const float* __restrict__ R, const __half* __restrict__ RH,
          float* __restrict__ C1, float* __restrict__ C2,
          __half* __restrict__ H1o, __half* __restrict__ H2o,
          __half* __restrict__ ZH,
          int NH, int K)
{
    extern __shared__ char smem[];
    const uint32_t sb = smem_u32(smem);
    const int tid  = threadIdx.x;
    const int wid  = tid >> 5;
    const int lane = tid & 31;
    const int bm = blockIdx.y * 256;
    const int bn = blockIdx.x * 128;
    const int wr = wid >> 2;          // warp row 0..3 (64 rows each)
    const int wc = wid & 3;           // warp col 0..3 (32 cols each)

    const int nch = K >> 6;           // BK = 64

    auto fill = [&](int ch) {
        const int k0 = ch << 6;
        const uint32_t st = sb + (uint32_t)(ch & 3) * STG_B;
        #pragma unroll
        for (int r = 0; r < 4; r++) {            // A: 2048 16B chunks
            const int c = tid + (r << 9);
            const int row = c >> 3, kc = c & 7;
            const uint32_t dst = (uint32_t)row * GSTRIDE + (uint32_t)(kc << 4);
            cp_async16(st + dst, Ah + (size_t)(bm + row) * K + k0 + (kc << 3));
        }
        #pragma unroll
        for (int r = 0; r < 2; r++) {            // B: 1024 16B chunks
            const int c = tid + (r << 9);
            const int row = c >> 3, kc = c & 7;
            const uint32_t dst = (uint32_t)row * GSTRIDE + (uint32_t)(kc << 4);
            cp_async16(st + TILE_A + dst, Bh + (size_t)(bn + row) * K + k0 + (kc << 3));
        }
        asm volatile("cp.async.commit_group;" ::: "memory");
    };

    float acc[4][4][4];
    #pragma unroll
    for (int i = 0; i < 4; i++)
        #pragma unroll
        for (int j = 0; j < 4; j++)
            #pragma unroll
            for (int q = 0; q < 4; q++) acc[i][j][q] = 0.0f;

    fill(0);
    if (nch > 1) fill(1);
    if (nch > 2) fill(2);

    const int l16  = lane & 15;
    const int ahi  = (lane >> 4) << 4;
    const int brow = ((lane >> 4) << 3) + (lane & 7);
    const int bhi  = ((lane >> 3) & 1) << 4;

    for (int i = 0; i < nch; i++) {
        if      (i + 2 < nch) asm volatile("cp.async.wait_group 2;" ::: "memory");
        else if (i + 1 < nch) asm volatile("cp.async.wait_group 1;" ::: "memory");
        else                  asm volatile("cp.async.wait_group 0;" ::: "memory");
        __syncthreads();   // single barrier per chunk (fill-distance-3, 4 buffers)

        const uint32_t st  = sb + (uint32_t)(i & 3) * STG_B;
        const uint32_t sAh = st;
        const uint32_t sBh = st + TILE_A;

        #pragma unroll
        for (int ks = 0; ks < 4; ks++) {
            uint32_t ah[4][4];
            #pragma unroll
            for (int mt = 0; mt < 4; mt++) {
                const uint32_t ra = (uint32_t)(wr*64 + mt*16 + l16) * GSTRIDE
                                  + (uint32_t)(ks*32 + ahi);
                ldm_x4(ah[mt][0], ah[mt][1], ah[mt][2], ah[mt][3], sAh + ra);
            }
            #pragma unroll
            for (int ntp = 0; ntp < 2; ntp++) {
                uint32_t bq[4];
                const uint32_t rb = (uint32_t)(wc*32 + ntp*16 + brow) * GSTRIDE
                                  + (uint32_t)(ks*32 + bhi);
                ldm_x4(bq[0], bq[1], bq[2], bq[3], sBh + rb);
                #pragma unroll
                for (int mt = 0; mt < 4; mt++) {
                    mma16816(acc[mt][2*ntp],   ah[mt], bq);
                    mma16816(acc[mt][2*ntp+1], ah[mt], bq + 2);
                }
            }
        }
        if (i + 3 < nch) fill(i + 3);
    }

    const int erow = lane >> 2;
    const int ecol = (lane & 3) << 1;

    if constexpr (GATED) {
        #pragma unroll
        for (int mt = 0; mt < 4; mt++) {
            #pragma unroll
            for (int nt = 0; nt < 4; nt++) {
                const int r0 = bm + wr*64 + mt*16 + erow;
                const int j  = ((bn + wc*32 + nt*8 + ecol) >> 1);
                const float f0 = geluf(acc[mt][nt][0]) * acc[mt][nt][1];
                const float f1 = geluf(acc[mt][nt][2]) * acc[mt][nt][3];
                const float f0n = __shfl_down_sync(0xffffffff, f0, 1);
                const float f1n = __shfl_down_sync(0xffffffff, f1, 1);
                if ((lane & 1) == 0) {
                    *(__half2*)(ZH + (size_t)r0     * NH + j) = __floats2half2_rn(f0, f0n);
                    *(__half2*)(ZH + (size_t)(r0+8) * NH + j) = __floats2half2_rn(f1, f1n);
                }
            }
        }
        return;
    }

    if constexpr (OUT16) {
        __half* Hout;
        int act, cb;
        if (bn < NH) { Hout = H1o; act = ACT1; cb = bn; }
        else         { Hout = H2o; act = ACT2; cb = bn - NH; }
        #pragma unroll
        for (int mt = 0; mt < 4; mt++) {
            #pragma unroll
            for (int nt = 0; nt < 4; nt++) {
                const int r0 = bm + wr*64 + mt*16 + erow;
                const int cc = cb + wc*32 + nt*8 + ecol;
                float v0 = acc[mt][nt][0], v1 = acc[mt][nt][1];
                float v2 = acc[mt][nt][2], v3 = acc[mt][nt][3];
                if (act == 1) { v0 = geluf(v0); v1 = geluf(v1); v2 = geluf(v2); v3 = geluf(v3); }
                if (RES) {
                    const float2 ra = *(const float2*)(R + (size_t)r0 * NH + cc);
                    const float2 rb = *(const float2*)(R + (size_t)(r0+8) * NH + cc);
                    v0 += ra.x; v1 += ra.y; v2 += rb.x; v3 += rb.y;
                }
                *(__half2*)(Hout + (size_t)r0     * NH + cc) =
                    __floats2half2_rn(v0, v1);
                *(__half2*)(Hout + (size_t)(r0+8) * NH + cc) =
                    __floats2half2_rn(v2, v3);
            }
        }
        return;
    }

    // fp32 epilogue (residual: fp32 R or fp16 RH)
    float* Cout;
    int act, cb;
    if (bn < NH) { Cout = C1; act = ACT1; cb = bn; }
    else         { Cout = C2; act = ACT2; cb = bn - NH; }

    #pragma unroll
    for (int mt = 0; mt < 4; mt++) {
        #pragma unroll
        for (int nt = 0; nt < 4; nt++) {
            const int r0 = bm + wr*64 + mt*16 + erow;
            const int cc = cb + wc*32 + nt*8 + ecol;
            float v0 = acc[mt][nt][0], v1 = acc[mt][nt][1];
            float v2 = acc[mt][nt][2], v3 = acc[mt][nt][3];
            if (act == 1) { v0 = geluf(v0); v1 = geluf(v1); v2 = geluf(v2); v3 = geluf(v3); }
            if (RES) {
                const float2 ra = *(const float2*)(R + (size_t)r0 * NH + cc);
                const float2 rb = *(const float2*)(R + (size_t)(r0+8) * NH + cc);
                v0 += ra.x; v1 += ra.y; v2 += rb.x; v3 += rb.y;
            }
            if (RESH) {
                const float2 ra = __half22float2(*(const __half2*)(RH + (size_t)r0 * NH + cc));
                const float2 rb = __half22float2(*(const __half2*)(RH + (size_t)(r0+8) * NH + cc));
                v0 += ra.x; v1 += ra.y; v2 += rb.x; v3 += rb.y;
            }
            *(float2*)(Cout + (size_t)r0     * NH + cc) = make_float2(v0, v1);
            *(float2*)(Cout + (size_t)(r0+8) * NH + cc) = make_float2(v2, v3);
        }
    }
}

// ---------------------------------------------------------------------------
// Weight transpose to fp16 with half2-vectorized stores (fused, one launch).
// ---------------------------------------------------------------------------
__device__ __forceinline__ void tsplit_body(const float* __restrict__ W,
                                            __half* __restrict__ Th,
                                            int Kd, int Nd, int rstride, int roff,
                                            int bx, int by)
{
    __shared__ float tile[32][33];   // [k_local][n_local]
    const int n0 = bx * 32, k0 = by * 32;
    const int tx = threadIdx.x, ty = threadIdx.y;   // (32, 8)
    #pragma unroll
    for (int i = 0; i < 32; i += 8)
        tile[ty + i][tx] = W[(size_t)(k0 + ty + i) * Nd + n0 + tx];
    __syncthreads();
    const int j  = tx & 15;
    const int nn = ty + ((tx >> 4) << 3);
    #pragma unroll
    for (int i = 0; i < 32; i += 16) {
        const float v0 = tile[2*j][nn + i];
        const float v1 = tile[2*j + 1][nn + i];
        const size_t o = ((size_t)(n0 + nn + i) * rstride + roff) * Kd + k0 + 2*j;
        *(__half2*)&Th[o] = __floats2half2_rn(v0, v1);
    }
}

__global__ void prep_all_kernel(const float* __restrict__ Wx, const float* __restrict__ Wy,
                                const float* __restrict__ Wa, const float* __restrict__ Wi,
                                const float* __restrict__ Wo, const float* __restrict__ Wg,
                                const float* __restrict__ Wu, const float* __restrict__ Wd,
                                __half* __restrict__ wh)
{
    int b = blockIdx.x;
    if (b < 5 * 1024) {
        const int w = b >> 10;
        const int t = b & 1023;
        const float* W;
        size_t off;
        switch (w) {
            case 0:  W = Wx; off = WOFF_X; break;
            case 1:  W = Wy; off = WOFF_Y; break;
            case 2:  W = Wa; off = WOFF_A; break;
            case 3:  W = Wi; off = WOFF_I; break;
            default: W = Wo; off = WOFF_O; break;
        }
        tsplit_body(W, wh + off, DD, DD, 1, 0, t & 31, t >> 5);
        return;
    }
    b -= 5 * 1024;
    if (b < 4096) {        // Wg: even interleaved rows
        tsplit_body(Wg, wh + WOFF_GU, DD, HH, 2, 0, b & 127, b >> 7);
        return;
    }
    b -= 4096;
    if (b < 4096) {        // Wu: odd interleaved rows
        tsplit_body(Wu, wh + WOFF_GU, DD, HH, 2, 1, b & 127, b >> 7);
        return;
    }
    b -= 4096;             // Wd
    tsplit_body(Wd, wh + WOFF_D, HH, DD, 1, 0, b & 31, b >> 5);
}

// ---------------------------------------------------------------------------
// RMSNorm fp32-in -> fp16-out (vectorized; D=1024, 256 threads)
// ---------------------------------------------------------------------------
__global__ void rmsnorm_f16_kernel(const float* __restrict__ x,
                                   const float* __restrict__ w,
                                   __half* __restrict__ oh)
{
    const int row = blockIdx.x;
    const float2* xr = (const float2*)(x + (size_t)row * DD);
    const float2* w2 = (const float2*)w;
    float ss = 0.0f;
    float2 v[2];
    #pragma unroll
    for (int r = 0; r < 2; r++) {
        v[r] = xr[threadIdx.x + r * 256];
        ss = fmaf(v[r].x, v[r].x, fmaf(v[r].y, v[r].y, ss));
    }
    #pragma unroll
    for (int off = 16; off > 0; off >>= 1)
        ss += __shfl_xor_sync(0xffffffff, ss, off);
    __shared__ float red[8];
    const int lane = threadIdx.x & 31, wid = threadIdx.x >> 5;
    if (lane == 0) red[wid] = ss;
    __syncthreads();
    if (wid == 0) {
        float s = (lane < 8) ? red[lane] : 0.0f;
        #pragma unroll
        for (int off = 4; off > 0; off >>= 1)
            s += __shfl_xor_sync(0xffffffff, s, off);
        if (lane == 0) red[0] = s;
    }
    __syncthreads();
    const float inv = rsqrtf(red[0] / (float)DD + 1e-6f);
    __half2* o2 = (__half2*)(oh + (size_t)row * DD);
    #pragma unroll
    for (int r = 0; r < 2; r++) {
        const float2 ww = w2[threadIdx.x + r * 256];
        o2[threadIdx.x + r * 256] =
            __floats2half2_rn(v[r].x * inv * ww.x, v[r].y * inv * ww.y);
    }
}

// ---------------------------------------------------------------------------
// RMSNorm fp16-in -> fp16-out (for h1 stored as fp16)
// ---------------------------------------------------------------------------
__global__ void rmsnorm_h16_kernel(const __half* __restrict__ x,
                                   const float* __restrict__ w,
                                   __half* __restrict__ oh)
{
    const int row = blockIdx.x;
    const __half2* xr = (const __half2*)(x + (size_t)row * DD);
    const float2* w2 = (const float2*)w;
    float ss = 0.0f;
    float2 v[2];
    #pragma unroll
    for (int r = 0; r < 2; r++) {
        v[r] = __half22float2(xr[threadIdx.x + r * 256]);
        ss = fmaf(v[r].x, v[r].x, fmaf(v[r].y, v[r].y, ss));
    }
    #pragma unroll
    for (int off = 16; off > 0; off >>= 1)
        ss += __shfl_xor_sync(0xffffffff, ss, off);
    __shared__ float red[8];
    const int lane = threadIdx.x & 31, wid = threadIdx.x >> 5;
    if (lane == 0) red[wid] = ss;
    __syncthreads();
    if (wid == 0) {
        float s = (lane < 8) ? red[lane] : 0.0f;
        #pragma unroll
        for (int off = 4; off > 0; off >>= 1)
            s += __shfl_xor_sync(0xffffffff, s, off);
        if (lane == 0) red[0] = s;
    }
    __syncthreads();
    const float inv = rsqrtf(red[0] / (float)DD + 1e-6f);
    __half2* o2 = (__half2*)(oh + (size_t)row * DD);
    #pragma unroll
    for (int r = 0; r < 2; r++) {
        const float2 ww = w2[threadIdx.x + r * 256];
        o2[threadIdx.x + r * 256] =
            __floats2half2_rn(v[r].x * inv * ww.x, v[r].y * inv * ww.y);
    }
}

// ---------------------------------------------------------------------------
// Causal depthwise conv (K=4), half2 vectorized, 4 sequence positions/thread.
// ---------------------------------------------------------------------------
#define S4 (SS/4)
__global__ void conv_f16_kernel(const __half2* __restrict__ in,
                                const float* __restrict__ cw,
                                const float* __restrict__ cb,
                                __half2* __restrict__ oh)
{
    const int idx = blockIdx.x * blockDim.x + threadIdx.x;
    if (idx >= BB * S4 * DD2) return;
    const int d2    = idx % DD2;
    const int s4    = (idx / DD2) % S4;
    const int batch = idx / (DD2 * S4);
    const int s0    = s4 * 4;
    const size_t base = ((size_t)batch * SS + s0) * DD2 + d2;

    float2 v[7];
    #pragma unroll
    for (int i = 0; i < 7; i++) {
        const int s = s0 + i - 3;
        v[i] = (s >= 0) ? __half22float2(in[base + (size_t)(i - 3) * DD2])
                        : make_float2(0.0f, 0.0f);
    }
    float w0[4], w1[4];
    #pragma unroll
    for (int k = 0; k < 4; k++) {
        w0[k] = cw[k * DD + 2*d2];
        w1[k] = cw[k * DD + 2*d2 + 1];
    }
    const float b0 = cb[2*d2], b1 = cb[2*d2 + 1];

    #pragma unroll
    for (int j = 0; j < 4; j++) {
        float a0 = b0, a1 = b1;
        #pragma unroll
        for (int k = 0; k < 4; k++) {
            a0 = fmaf(w0[k], v[j + k].x, a0);
            a1 = fmaf(w1[k], v[j + k].y, a1);
        }
        oh[base + (size_t)j * DD2] = __floats2half2_rn(a0, a1);
    }
}

// ---------------------------------------------------------------------------
// Scan pass 1 (half2): gates + chunk-local scan.
// ---------------------------------------------------------------------------
__global__ void scan1_kernel(__half2* __restrict__ rlin_a,
                             const __half2* __restrict__ ilin,
                             const __half2* __restrict__ xc,
                             const float* __restrict__ lam,
                             __half2* __restrict__ lh,
                             float2* __restrict__ sa,
                             float2* __restrict__ sh)
{
    const int idx = blockIdx.x * blockDim.x + threadIdx.x;
    if (idx >= BB * NC * DD2) return;
    const int d2    = idx % DD2;
    const int chunk = (idx / DD2) % NC;
    const int batch = idx / (DD2 * NC);
    const float cf0 = -8.0f * softplusf(lam[2*d2]);
    const float cf1 = -8.0f * softplusf(lam[2*d2 + 1]);
    const size_t base = ((size_t)batch * SS + (size_t)chunk * CL) * DD2 + d2;

    float p0 = 1.0f, p1 = 1.0f, h0 = 0.0f, h1 = 0.0f;
    for (int t = 0; t < CL; t++) {
        const size_t off = base + (size_t)t * DD2;
        const float2 rv = __half22float2(rlin_a[off]);
        const float2 iv = __half22float2(ilin[off]);
        const float2 xv = __half22float2(xc[off]);
        const float a0 = expf(cf0 * sigmoidf(rv.x));
        const float a1 = expf(cf1 * sigmoidf(rv.y));
        const float b0 = sqrtf(fmaxf(1.0f - a0*a0, 1e-12f)) * sigmoidf(iv.x) * xv.x;
        const float b1 = sqrtf(fmaxf(1.0f - a1*a1, 1e-12f)) * sigmoidf(iv.y) * xv.y;
        h0 = fmaf(a0, h0, b0);
        h1 = fmaf(a1, h1, b1);
        p0 *= a0; p1 *= a1;
        rlin_a[off] = __floats2half2_rn(a0, a1);
        lh[off]     = __floats2half2_rn(h0, h1);
    }
    sa[idx] = make_float2(p0, p1);
    sh[idx] = make_float2(h0, h1);
}

// ---------------------------------------------------------------------------
// Scan pass 2 (float2): combine chunk carries.
// ---------------------------------------------------------------------------
__global__ void scan2_kernel(const float2* __restrict__ sa, float2* __restrict__ sh)
{
    const int idx = blockIdx.x * blockDim.x + threadIdx.x;
    if (idx >= BB * DD2) return;
    const int d2 = idx % DD2, batch = idx / DD2;
    float H0 = 0.0f, H1 = 0.0f;
    for (int c = 0; c < NC; c++) {
        const size_t o = ((size_t)batch * NC + c) * DD2 + d2;
        const float2 av = sa[o];
        const float2 hv = sh[o];
        H0 = fmaf(av.x, H0, hv.x);
        H1 = fmaf(av.y, H1, hv.y);
        sh[o] = make_float2(H0, H1);
    }
}

// ---------------------------------------------------------------------------
// Scan pass 3 (half2): apply carries, z = h * yb, fp16 out.
// ---------------------------------------------------------------------------
__global__ void scan3_kernel(const __half2* __restrict__ aArr,
                             const __half2* __restrict__ lhArr,
                             const float2* __restrict__ sh,
                             const __half2* __restrict__ yb,
                             __half2* __restrict__ zh)
{
    const int idx = blockIdx.x * blockDim.x + threadIdx.x;
    if (idx >= BB * NC * DD2) return;
    const int d2    = idx % DD2;
    const int chunk = (idx / DD2) % NC;
    const int batch = idx / (DD2 * NC);
    float c0 = 0.0f, c1 = 0.0f;
    if (chunk != 0) {
        const float2 cv = sh[((size_t)batch * NC + chunk - 1) * DD2 + d2];
        c0 = cv.x; c1 = cv.y;
    }
    const size_t base = ((size_t)batch * SS + (size_t)chunk * CL) * DD2 + d2;

    float p0 = 1.0f, p1 = 1.0f;
    for (int t = 0; t < CL; t++) {
        const size_t off = base + (size_t)t * DD2;
        const float2 av = __half22float2(aArr[off]);
        const float2 lv = __half22float2(lhArr[off]);
        const float2 yv = __half22float2(yb[off]);
        p0 *= av.x; p1 *= av.y;
        const float z0 = fmaf(p0, c0, lv.x) * yv.x;
        const float z1 = fmaf(p1, c1, lv.y) * yv.y;
        zh[off] = __floats2half2_rn(z0, z1);
    }
}

// ---------------------------------------------------------------------------
// Launch
// ---------------------------------------------------------------------------
extern "C" void kernel_launch(void* const* d_in, const int* in_sizes, int n_in,
                              void* d_out, int out_size)
{
    const float* x       = (const float*)d_in[0];
    const float* norm1_w = (const float*)d_in[1];
    const float* Wx      = (const float*)d_in[2];
    const float* Wy      = (const float*)d_in[3];
    const float* conv_w  = (const float*)d_in[4];
    const float* conv_b  = (const float*)d_in[5];
    const float* Wi      = (const float*)d_in[6];
    const float* Wa      = (const float*)d_in[7];
    const float* lam     = (const float*)d_in[8];
    const float* Wo      = (const float*)d_in[9];
    const float* norm2_w = (const float*)d_in[10];
    const float* Wg      = (const float*)d_in[11];
    const float* Wu      = (const float*)d_in[12];
    const float* Wd      = (const float*)d_in[13];
    float* out = (float*)d_out;

    float *sa, *sh;
    __half *ah, *xbh, *ybh, *rl, *il, *lh, *zh, *wh;
    cudaGetSymbolAddress((void**)&sa,  g_sa);
    cudaGetSymbolAddress((void**)&sh,  g_sh);
    cudaGetSymbolAddress((void**)&ah,  g_ah);
    cudaGetSymbolAddress((void**)&xbh, g_xbh);
    cudaGetSymbolAddress((void**)&ybh, g_ybh);
    cudaGetSymbolAddress((void**)&rl,  g_rl);
    cudaGetSymbolAddress((void**)&il,  g_il);
    cudaGetSymbolAddress((void**)&lh,  g_lh);
    cudaGetSymbolAddress((void**)&zh,  g_zh);
    cudaGetSymbolAddress((void**)&wh,  g_wh);
    __half* h1h = xbh;   // xb buffer is dead after conv; reuse for fp16 h1

    cudaFuncSetAttribute(hmma_gemm<0,1,false,false,false,true>,  cudaFuncAttributeMaxDynamicSharedMemorySize, GEMM_SMEM);
    cudaFuncSetAttribute(hmma_gemm<0,0,false,false,false,true>,  cudaFuncAttributeMaxDynamicSharedMemorySize, GEMM_SMEM);
    cudaFuncSetAttribute(hmma_gemm<0,0,true,false,false,true>,   cudaFuncAttributeMaxDynamicSharedMemorySize, GEMM_SMEM);
    cudaFuncSetAttribute(hmma_gemm<0,0,false,false,true,false>,  cudaFuncAttributeMaxDynamicSharedMemorySize, GEMM_SMEM);
    cudaFuncSetAttribute(hmma_gemm<0,0,false,true,false,false>,  cudaFuncAttributeMaxDynamicSharedMemorySize, GEMM_SMEM);

    const dim3 tsb(32, 8);
    const int gCV = (BB * S4 * DD2 + 255) / 256;     // conv: 4 s-positions/thread
    const int gSC2 = (BB * NC * DD2 + 255) / 256;

    const dim3 gemXY(2048 / 128, MM / 256);   // dual Wx|Wy (fp16 out)
    const dim3 gemAI(2048 / 128, MM / 256);   // dual Wa|Wi (fp16 out)
    const dim3 gemGU(8192 / 128, MM / 256);   // interleaved Wg|Wu (gated)
    const dim3 gemO (1024 / 128, MM / 256);   // Wo (K=1024, fp16 out + fp32 res)
    const dim3 gemDn(1024 / 128, MM / 256);   // Wd (K=4096, fp32 out + fp16 res)

    // all weight prep in ONE launch + rmsnorm1
    prep_all_kernel<<<5*1024 + 3*4096, tsb>>>(Wx, Wy, Wa, Wi, Wo, Wg, Wu, Wd, wh);
    rmsnorm_f16_kernel<<<MM, 256>>>(x, norm1_w, ah);
    // xb = t @ Wx ; yb = gelu(t @ Wy)  [dual, fp16 out]
    hmma_gemm<0,1,false,false,false,true><<<gemXY, 512, GEMM_SMEM>>>(ah, wh + WOFF_X,
        nullptr, nullptr, nullptr, nullptr, xbh, ybh, nullptr, DD, DD);
    // conv -> ah (fp16)
    conv_f16_kernel<<<gCV, 256>>>((const __half2*)xbh, conv_w, conv_b, (__half2*)ah);
    // rlin -> rl ; ilin -> il  [dual, fp16 out]
    hmma_gemm<0,0,false,false,false,true><<<gemAI, 512, GEMM_SMEM>>>(ah, wh + WOFF_A,
        nullptr, nullptr, nullptr, nullptr, rl, il, nullptr, DD, DD);
    // gates + chunked scan + z = h*yb -> ah (fp16)
    scan1_kernel<<<gSC2, 256>>>((__half2*)rl, (const __half2*)il, (const __half2*)ah,
                                lam, (__half2*)lh, (float2*)sa, (float2*)sh);
    scan2_kernel<<<(BB * DD2 + 255) / 256, 256>>>((const float2*)sa, (float2*)sh);
    scan3_kernel<<<gSC2, 256>>>((const __half2*)rl, (const __half2*)lh,
                                (const float2*)sh, (const __half2*)ybh, (__half2*)ah);
    // h1 = x + z @ Wo  -> fp16 (xb buffer reused)
    hmma_gemm<0,0,true,false,false,true><<<gemO, 512, GEMM_SMEM>>>(ah, wh + WOFF_O,
        x, nullptr, nullptr, nullptr, h1h, h1h, nullptr, DD, DD);
    // u = rmsnorm(h1) -> ah   (fp16 input)
    rmsnorm_h16_kernel<<<MM, 256>>>(h1h, norm2_w, ah);
    // ff = gelu(u @ Wg) * (u @ Wu) -> zh  [gated]
    hmma_gemm<0,0,false,false,true,false><<<gemGU, 512, GEMM_SMEM>>>(ah, wh + WOFF_GU,
        nullptr, nullptr, nullptr, nullptr, nullptr, nullptr, zh, HH, DD);
    // out = h1 + ff @ Wd   (fp16 residual)
    hmma_gemm<0,0,false,true,false,false><<<gemDn, 512, GEMM_SMEM>>>(zh, wh + WOFF_D,
        nullptr, h1h, out, out, nullptr, nullptr, nullptr, DD, HH);
}

// round 16
// speedup vs baseline: 1.0190x; 1.0175x over previous
#include <cuda_runtime.h>
#include <cuda_fp16.h>
#include <math.h>
#include <stdint.h>

// Problem dims (fixed by the dataset)
#define BB 4
#define SS 2048
#define DD 1024
#define HH 4096
#define MM (BB*SS)          // 8192 rows
#define NC 32               // scan chunks
#define CL (SS/NC)          // 64 steps per chunk
#define DD2 (DD/2)

// ---------------------------------------------------------------------------
// Scratch (static device globals; no allocation in kernel_launch)
// ---------------------------------------------------------------------------
__device__ __align__(16) float g_h1 [(size_t)MM*DD];    // h1 trunk (fp32)
__device__ __align__(16) float g_sa [(size_t)BB*NC*DD]; // chunk a-products
__device__ __align__(16) float g_sh [(size_t)BB*NC*DD]; // chunk h-carries

// fp16 streams
__device__ __align__(16) __half g_ah [(size_t)MM*DD];  // rmsnorm out / conv out / z
__device__ __align__(16) __half g_xbh[(size_t)MM*DD];  // xb (gemXY C1)
__device__ __align__(16) __half g_ybh[(size_t)MM*DD];  // yb (gemXY C2, gelu)
__device__ __align__(16) __half g_rl [(size_t)MM*DD];  // rlin -> a (in place)
__device__ __align__(16) __half g_il [(size_t)MM*DD];  // ilin
__device__ __align__(16) __half g_lh [(size_t)MM*DD];  // scan local h (fp16)
__device__ __align__(16) __half g_zh [(size_t)MM*HH];  // gated-MLP intermediate
// fp16 transposed weights, packed arena (17M halfs)
#define WOFF_X  ((size_t)0)
#define WOFF_Y  ((size_t)1*1024*1024)   // follows X (dual Wx|Wy)
#define WOFF_A  ((size_t)2*1024*1024)
#define WOFF_I  ((size_t)3*1024*1024)   // follows A (dual Wa|Wi)
#define WOFF_O  ((size_t)4*1024*1024)
#define WOFF_GU ((size_t)5*1024*1024)   // Wg/Wu column-interleaved (8192 rows)
#define WOFF_D  ((size_t)13*1024*1024)
__device__ __align__(16) __half g_wh[(size_t)17*1024*1024];

// ---------------------------------------------------------------------------
// Math helpers
// ---------------------------------------------------------------------------
__device__ __forceinline__ float geluf(float x) {
    const float c = 0.7978845608028654f; // sqrt(2/pi)
    float x3 = x * x * x;
    float t  = tanhf(c * (x + 0.044715f * x3));
    return 0.5f * x * (1.0f + t);
}
__device__ __forceinline__ float sigmoidf(float x) {
    return 1.0f / (1.0f + expf(-x));
}
__device__ __forceinline__ float softplusf(float x) {
    return fmaxf(x, 0.0f) + log1pf(expf(-fabsf(x)));
}

// ---------------------------------------------------------------------------
// PTX helpers (baseline compute_103 features only)
// ---------------------------------------------------------------------------
__device__ __forceinline__ uint32_t smem_u32(const void* p) {
    uint32_t a;
    asm("{ .reg .u64 t; cvta.to.shared.u64 t, %1; cvt.u32.u64 %0, t; }" : "=r"(a) : "l"(p));
    return a;
}
__device__ __forceinline__ void cp_async16(uint32_t dst, const void* src) {
    asm volatile("cp.async.cg.shared.global [%0], [%1], 16;" :: "r"(dst), "l"(src) : "memory");
}
__device__ __forceinline__ void ldm_x4(uint32_t& r0, uint32_t& r1, uint32_t& r2, uint32_t& r3,
                                       uint32_t addr) {
    asm volatile("ldmatrix.sync.aligned.m8n8.x4.shared.b16 {%0,%1,%2,%3}, [%4];"
                 : "=r"(r0), "=r"(r1), "=r"(r2), "=r"(r3) : "r"(addr));
}
__device__ __forceinline__ void mma16816(float* c, const uint32_t* a, const uint32_t* b) {
    asm volatile(
        "mma.sync.aligned.m16n8k16.row.col.f32.f16.f16.f32 "
        "{%0,%1,%2,%3}, {%4,%5,%6,%7}, {%8,%9}, {%0,%1,%2,%3};"
        : "+f"(c[0]), "+f"(c[1]), "+f"(c[2]), "+f"(c[3])
        : "r"(a[0]), "r"(a[1]), "r"(a[2]), "r"(a[3]), "r"(b[0]), "r"(b[1]));
}

// ---------------------------------------------------------------------------
// Single-product fp16 HMMA GEMM: C = act(A @ W^T) (+R).
// CTA 256x128, BK=64, 16 warps (4Mx4N, warp tile 64x32), 4-stage cp.async,
// fill-distance 3, single __syncthreads per chunk, 1 CTA/SM  (R13 config).
// ---------------------------------------------------------------------------
#define GSTRIDE 144u
#define TILE_A  36864u            // 256 rows * 144B
#define STG_B   55296u            // A(36864) + B(18432)
#define GEMM_SMEM (4*STG_B)       // 221184

template<int ACT1, int ACT2, bool RES, bool GATED, bool OUT16>
__global__ void __launch_bounds__(512, 1)
hmma_gemm(const __half* __restrict__ Ah, const __half* __restrict__ Bh,
          const float* __restrict__ R, float* __restrict__ C1, float* __restrict__ C2,
          __half* __restrict__ H1o, __half* __restrict__ H2o,
          __half* __restrict__ ZH,
          int NH, int K)
{
    extern __shared__ char smem[];
    const uint32_t sb = smem_u32(smem);
    const int tid  = threadIdx.x;
    const int wid  = tid >> 5;
    const int lane = tid & 31;
    const int bm = blockIdx.y * 256;
    const int bn = blockIdx.x * 128;
    const int wr = wid >> 2;          // warp row 0..3 (64 rows each)
    const int wc = wid & 3;           // warp col 0..3 (32 cols each)

    const int nch = K >> 6;           // BK = 64

    auto fill = [&](int ch) {
        const int k0 = ch << 6;
        const uint32_t st = sb + (uint32_t)(ch & 3) * STG_B;
        #pragma unroll
        for (int r = 0; r < 4; r++) {            // A: 2048 16B chunks
            const int c = tid + (r << 9);
            const int row = c >> 3, kc = c & 7;
            const uint32_t dst = (uint32_t)row * GSTRIDE + (uint32_t)(kc << 4);
            cp_async16(st + dst, Ah + (size_t)(bm + row) * K + k0 + (kc << 3));
        }
        #pragma unroll
        for (int r = 0; r < 2; r++) {            // B: 1024 16B chunks
            const int c = tid + (r << 9);
            const int row = c >> 3, kc = c & 7;
            const uint32_t dst = (uint32_t)row * GSTRIDE + (uint32_t)(kc << 4);
            cp_async16(st + TILE_A + dst, Bh + (size_t)(bn + row) * K + k0 + (kc << 3));
        }
        asm volatile("cp.async.commit_group;" ::: "memory");
    };

    float acc[4][4][4];
    #pragma unroll
    for (int i = 0; i < 4; i++)
        #pragma unroll
        for (int j = 0; j < 4; j++)
            #pragma unroll
            for (int q = 0; q < 4; q++) acc[i][j][q] = 0.0f;

    fill(0);
    if (nch > 1) fill(1);
    if (nch > 2) fill(2);

    const int l16  = lane & 15;
    const int ahi  = (lane >> 4) << 4;
    const int brow = ((lane >> 4) << 3) + (lane & 7);
    const int bhi  = ((lane >> 3) & 1) << 4;

    for (int i = 0; i < nch; i++) {
        if      (i + 2 < nch) asm volatile("cp.async.wait_group 2;" ::: "memory");
        else if (i + 1 < nch) asm volatile("cp.async.wait_group 1;" ::: "memory");
        else                  asm volatile("cp.async.wait_group 0;" ::: "memory");
        __syncthreads();   // single barrier per chunk (fill-distance-3, 4 buffers)

        const uint32_t st  = sb + (uint32_t)(i & 3) * STG_B;
        const uint32_t sAh = st;
        const uint32_t sBh = st + TILE_A;

        #pragma unroll
        for (int ks = 0; ks < 4; ks++) {
            uint32_t ah[4][4];
            #pragma unroll
            for (int mt = 0; mt < 4; mt++) {
                const uint32_t ra = (uint32_t)(wr*64 + mt*16 + l16) * GSTRIDE
                                  + (uint32_t)(ks*32 + ahi);
                ldm_x4(ah[mt][0], ah[mt][1], ah[mt][2], ah[mt][3], sAh + ra);
            }
            #pragma unroll
            for (int ntp = 0; ntp < 2; ntp++) {
                uint32_t bq[4];
                const uint32_t rb = (uint32_t)(wc*32 + ntp*16 + brow) * GSTRIDE
                                  + (uint32_t)(ks*32 + bhi);
                ldm_x4(bq[0], bq[1], bq[2], bq[3], sBh + rb);
                #pragma unroll
                for (int mt = 0; mt < 4; mt++) {
                    mma16816(acc[mt][2*ntp],   ah[mt], bq);
                    mma16816(acc[mt][2*ntp+1], ah[mt], bq + 2);
                }
            }
        }
        if (i + 3 < nch) fill(i + 3);
    }

    const int erow = lane >> 2;
    const int ecol = (lane & 3) << 1;

    if constexpr (GATED) {
        #pragma unroll
        for (int mt = 0; mt < 4; mt++) {
            #pragma unroll
            for (int nt = 0; nt < 4; nt++) {
                const int r0 = bm + wr*64 + mt*16 + erow;
                const int j  = ((bn + wc*32 + nt*8 + ecol) >> 1);
                const float f0 = geluf(acc[mt][nt][0]) * acc[mt][nt][1];
                const float f1 = geluf(acc[mt][nt][2]) * acc[mt][nt][3];
                const float f0n = __shfl_down_sync(0xffffffff, f0, 1);
                const float f1n = __shfl_down_sync(0xffffffff, f1, 1);
                if ((lane & 1) == 0) {
                    *(__half2*)(ZH + (size_t)r0     * NH + j) = __floats2half2_rn(f0, f0n);
                    *(__half2*)(ZH + (size_t)(r0+8) * NH + j) = __floats2half2_rn(f1, f1n);
                }
            }
        }
        return;
    }

    if constexpr (OUT16) {
        __half* Hout;
        int act, cb;
        if (bn < NH) { Hout = H1o; act = ACT1; cb = bn; }
        else         { Hout = H2o; act = ACT2; cb = bn - NH; }
        #pragma unroll
        for (int mt = 0; mt < 4; mt++) {
            #pragma unroll
            for (int nt = 0; nt < 4; nt++) {
                const int r0 = bm + wr*64 + mt*16 + erow;
                const int cc = cb + wc*32 + nt*8 + ecol;
                float v0 = acc[mt][nt][0], v1 = acc[mt][nt][1];
                float v2 = acc[mt][nt][2], v3 = acc[mt][nt][3];
                if (act == 1) { v0 = geluf(v0); v1 = geluf(v1); v2 = geluf(v2); v3 = geluf(v3); }
                *(__half2*)(Hout + (size_t)r0     * NH + cc) =
                    __floats2half2_rn(v0, v1);
                *(__half2*)(Hout + (size_t)(r0+8) * NH + cc) =
                    __floats2half2_rn(v2, v3);
            }
        }
        return;
    }

    // fp32 epilogue (with residual)
    float* Cout;
    int act, cb;
    if (bn < NH) { Cout = C1; act = ACT1; cb = bn; }
    else         { Cout = C2; act = ACT2; cb = bn - NH; }

    #pragma unroll
    for (int mt = 0; mt < 4; mt++) {
        #pragma unroll
        for (int nt = 0; nt < 4; nt++) {
            const int r0 = bm + wr*64 + mt*16 + erow;
            const int cc = cb + wc*32 + nt*8 + ecol;
            float v0 = acc[mt][nt][0], v1 = acc[mt][nt][1];
            float v2 = acc[mt][nt][2], v3 = acc[mt][nt][3];
            if (act == 1) { v0 = geluf(v0); v1 = geluf(v1); v2 = geluf(v2); v3 = geluf(v3); }
            if (RES) {
                const float2 ra = *(const float2*)(R + (size_t)r0 * NH + cc);
                const float2 rb = *(const float2*)(R + (size_t)(r0+8) * NH + cc);
                v0 += ra.x; v1 += ra.y; v2 += rb.x; v3 += rb.y;
            }
            *(float2*)(Cout + (size_t)r0     * NH + cc) = make_float2(v0, v1);
            *(float2*)(Cout + (size_t)(r0+8) * NH + cc) = make_float2(v2, v3);
        }
    }
}

// ---------------------------------------------------------------------------
// Weight transpose to fp16 with half2-vectorized stores (fused, one launch).
// ---------------------------------------------------------------------------
__device__ __forceinline__ void tsplit_body(const float* __restrict__ W,
                                            __half* __restrict__ Th,
                                            int Kd, int Nd, int rstride, int roff,
                                            int bx, int by)
{
    __shared__ float tile[32][33];   // [k_local][n_local]
    const int n0 = bx * 32, k0 = by * 32;
    const int tx = threadIdx.x, ty = threadIdx.y;   // (32, 8)
    #pragma unroll
    for (int i = 0; i < 32; i += 8)
        tile[ty + i][tx] = W[(size_t)(k0 + ty + i) * Nd + n0 + tx];
    __syncthreads();
    const int j  = tx & 15;
    const int nn = ty + ((tx >> 4) << 3);
    #pragma unroll
    for (int i = 0; i < 32; i += 16) {
        const float v0 = tile[2*j][nn + i];
        const float v1 = tile[2*j + 1][nn + i];
        const size_t o = ((size_t)(n0 + nn + i) * rstride + roff) * Kd + k0 + 2*j;
        *(__half2*)&Th[o] = __floats2half2_rn(v0, v1);
    }
}

__global__ void prep_all_kernel(const float* __restrict__ Wx, const float* __restrict__ Wy,
                                const float* __restrict__ Wa, const float* __restrict__ Wi,
                                const float* __restrict__ Wo, const float* __restrict__ Wg,
                                const float* __restrict__ Wu, const float* __restrict__ Wd,
                                __half* __restrict__ wh)
{
    int b = blockIdx.x;
    if (b < 5 * 1024) {
        const int w = b >> 10;
        const int t = b & 1023;
        const float* W;
        size_t off;
        switch (w) {
            case 0:  W = Wx; off = WOFF_X; break;
            case 1:  W = Wy; off = WOFF_Y; break;
            case 2:  W = Wa; off = WOFF_A; break;
            case 3:  W = Wi; off = WOFF_I; break;
            default: W = Wo; off = WOFF_O; break;
        }
        tsplit_body(W, wh + off, DD, DD, 1, 0, t & 31, t >> 5);
        return;
    }
    b -= 5 * 1024;
    if (b < 4096) {        // Wg: even interleaved rows
        tsplit_body(Wg, wh + WOFF_GU, DD, HH, 2, 0, b & 127, b >> 7);
        return;
    }
    b -= 4096;
    if (b < 4096) {        // Wu: odd interleaved rows
        tsplit_body(Wu, wh + WOFF_GU, DD, HH, 2, 1, b & 127, b >> 7);
        return;
    }
    b -= 4096;             // Wd
    tsplit_body(Wd, wh + WOFF_D, HH, DD, 1, 0, b & 31, b >> 5);
}

// ---------------------------------------------------------------------------
// RMSNorm with fp16 output (float2 / half2 vectorized; D=1024, 256 threads)
// ---------------------------------------------------------------------------
__global__ void rmsnorm_f16_kernel(const float* __restrict__ x,
                                   const float* __restrict__ w,
                                   __half* __restrict__ oh)
{
    const int row = blockIdx.x;
    const float2* xr = (const float2*)(x + (size_t)row * DD);
    const float2* w2 = (const float2*)w;
    float ss = 0.0f;
    float2 v[2];
    #pragma unroll
    for (int r = 0; r < 2; r++) {
        v[r] = xr[threadIdx.x + r * 256];
        ss = fmaf(v[r].x, v[r].x, fmaf(v[r].y, v[r].y, ss));
    }
    #pragma unroll
    for (int off = 16; off > 0; off >>= 1)
        ss += __shfl_xor_sync(0xffffffff, ss, off);
    __shared__ float red[8];
    const int lane = threadIdx.x & 31, wid = threadIdx.x >> 5;
    if (lane == 0) red[wid] = ss;
    __syncthreads();
    if (wid == 0) {
        float s = (lane < 8) ? red[lane] : 0.0f;
        #pragma unroll
        for (int off = 4; off > 0; off >>= 1)
            s += __shfl_xor_sync(0xffffffff, s, off);
        if (lane == 0) red[0] = s;
    }
    __syncthreads();
    const float inv = rsqrtf(red[0] / (float)DD + 1e-6f);
    __half2* o2 = (__half2*)(oh + (size_t)row * DD);
    #pragma unroll
    for (int r = 0; r < 2; r++) {
        const float2 ww = w2[threadIdx.x + r * 256];
        o2[threadIdx.x + r * 256] =
            __floats2half2_rn(v[r].x * inv * ww.x, v[r].y * inv * ww.y);
    }
}

// ---------------------------------------------------------------------------
// Causal depthwise conv (K=4), half2 vectorized, 4 sequence positions/thread.
// Hot path (s0 >= 3) loads all 7 input rows unconditionally.
// ---------------------------------------------------------------------------
#define S4 (SS/4)
__global__ void conv_f16_kernel(const __half2* __restrict__ in,
                                const float* __restrict__ cw,
                                const float* __restrict__ cb,
                                __half2* __restrict__ oh)
{
    const int idx = blockIdx.x * blockDim.x + threadIdx.x;
    if (idx >= BB * S4 * DD2) return;
    const int d2    = idx % DD2;
    const int s4    = (idx / DD2) % S4;
    const int batch = idx / (DD2 * S4);
    const int s0    = s4 * 4;
    const size_t base = ((size_t)batch * SS + s0) * DD2 + d2;

    float2 v[7];
    if (s0 >= 3) {
        #pragma unroll
        for (int i = 0; i < 7; i++)
            v[i] = __half22float2(in[base + (size_t)(i - 3) * DD2]);
    } else {
        #pragma unroll
        for (int i = 0; i < 7; i++)
            v[i] = (s0 + i - 3 >= 0)
                 ? __half22float2(in[base + (size_t)(i - 3) * DD2])
                 : make_float2(0.0f, 0.0f);
    }
    float w0[4], w1[4];
    #pragma unroll
    for (int k = 0; k < 4; k++) {
        w0[k] = cw[k * DD + 2*d2];
        w1[k] = cw[k * DD + 2*d2 + 1];
    }
    const float b0 = cb[2*d2], b1 = cb[2*d2 + 1];

    #pragma unroll
    for (int j = 0; j < 4; j++) {
        float a0 = b0, a1 = b1;
        #pragma unroll
        for (int k = 0; k < 4; k++) {
            a0 = fmaf(w0[k], v[j + k].x, a0);
            a1 = fmaf(w1[k], v[j + k].y, a1);
        }
        oh[base + (size_t)j * DD2] = __floats2half2_rn(a0, a1);
    }
}

// ---------------------------------------------------------------------------
// Scan pass 1 (half2): gates + chunk-local scan.
// ---------------------------------------------------------------------------
__global__ void scan1_kernel(__half2* __restrict__ rlin_a,
                             const __half2* __restrict__ ilin,
                             const __half2* __restrict__ xc,
                             const float* __restrict__ lam,
                             __half2* __restrict__ lh,
                             float2* __restrict__ sa,
                             float2* __restrict__ sh)
{
    const int idx = blockIdx.x * blockDim.x + threadIdx.x;
    if (idx >= BB * NC * DD2) return;
    const int d2    = idx % DD2;
    const int chunk = (idx / DD2) % NC;
    const int batch = idx / (DD2 * NC);
    const float cf0 = -8.0f * softplusf(lam[2*d2]);
    const float cf1 = -8.0f * softplusf(lam[2*d2 + 1]);
    const size_t base = ((size_t)batch * SS + (size_t)chunk * CL) * DD2 + d2;

    float p0 = 1.0f, p1 = 1.0f, h0 = 0.0f, h1 = 0.0f;
    for (int t = 0; t < CL; t++) {
        const size_t off = base + (size_t)t * DD2;
        const float2 rv = __half22float2(rlin_a[off]);
        const float2 iv = __half22float2(ilin[off]);
        const float2 xv = __half22float2(xc[off]);
        const float a0 = expf(cf0 * sigmoidf(rv.x));
        const float a1 = expf(cf1 * sigmoidf(rv.y));
        const float b0 = sqrtf(fmaxf(1.0f - a0*a0, 1e-12f)) * sigmoidf(iv.x) * xv.x;
        const float b1 = sqrtf(fmaxf(1.0f - a1*a1, 1e-12f)) * sigmoidf(iv.y) * xv.y;
        h0 = fmaf(a0, h0, b0);
        h1 = fmaf(a1, h1, b1);
        p0 *= a0; p1 *= a1;
        rlin_a[off] = __floats2half2_rn(a0, a1);
        lh[off]     = __floats2half2_rn(h0, h1);
    }
    sa[idx] = make_float2(p0, p1);
    sh[idx] = make_float2(h0, h1);
}

// ---------------------------------------------------------------------------
// Scan pass 2 (float2): combine chunk carries.
// ---------------------------------------------------------------------------
__global__ void scan2_kernel(const float2* __restrict__ sa, float2* __restrict__ sh)
{
    const int idx = blockIdx.x * blockDim.x + threadIdx.x;
    if (idx >= BB * DD2) return;
    const int d2 = idx % DD2, batch = idx / DD2;
    float H0 = 0.0f, H1 = 0.0f;
    for (int c = 0; c < NC; c++) {
        const size_t o = ((size_t)batch * NC + c) * DD2 + d2;
        const float2 av = sa[o];
        const float2 hv = sh[o];
        H0 = fmaf(av.x, H0, hv.x);
        H1 = fmaf(av.y, H1, hv.y);
        sh[o] = make_float2(H0, H1);
    }
}

// ---------------------------------------------------------------------------
// Scan pass 3 (half2): apply carries, z = h * yb, fp16 out.
// ---------------------------------------------------------------------------
__global__ void scan3_kernel(const __half2* __restrict__ aArr,
                             const __half2* __restrict__ lhArr,
                             const float2* __restrict__ sh,
                             const __half2* __restrict__ yb,
                             __half2* __restrict__ zh)
{
    const int idx = blockIdx.x * blockDim.x + threadIdx.x;
    if (idx >= BB * NC * DD2) return;
    const int d2    = idx % DD2;
    const int chunk = (idx / DD2) % NC;
    const int batch = idx / (DD2 * NC);
    float c0 = 0.0f, c1 = 0.0f;
    if (chunk != 0) {
        const float2 cv = sh[((size_t)batch * NC + chunk - 1) * DD2 + d2];
        c0 = cv.x; c1 = cv.y;
    }
    const size_t base = ((size_t)batch * SS + (size_t)chunk * CL) * DD2 + d2;

    float p0 = 1.0f, p1 = 1.0f;
    for (int t = 0; t < CL; t++) {
        const size_t off = base + (size_t)t * DD2;
        const float2 av = __half22float2(aArr[off]);
        const float2 lv = __half22float2(lhArr[off]);
        const float2 yv = __half22float2(yb[off]);
        p0 *= av.x; p1 *= av.y;
        const float z0 = fmaf(p0, c0, lv.x) * yv.x;
        const float z1 = fmaf(p1, c1, lv.y) * yv.y;
        zh[off] = __floats2half2_rn(z0, z1);
    }
}

// ---------------------------------------------------------------------------
// Launch
// ---------------------------------------------------------------------------
extern "C" void kernel_launch(void* const* d_in, const int* in_sizes, int n_in,
                              void* d_out, int out_size)
{
    const float* x       = (const float*)d_in[0];
    const float* norm1_w = (const float*)d_in[1];
    const float* Wx      = (const float*)d_in[2];
    const float* Wy      = (const float*)d_in[3];
    const float* conv_w  = (const float*)d_in[4];
    const float* conv_b  = (const float*)d_in[5];
    const float* Wi      = (const float*)d_in[6];
    const float* Wa      = (const float*)d_in[7];
    const float* lam     = (const float*)d_in[8];
    const float* Wo      = (const float*)d_in[9];
    const float* norm2_w = (const float*)d_in[10];
    const float* Wg      = (const float*)d_in[11];
    const float* Wu      = (const float*)d_in[12];
    const float* Wd      = (const float*)d_in[13];
    float* out = (float*)d_out;

    float *h1, *sa, *sh;
    __half *ah, *xbh, *ybh, *rl, *il, *lh, *zh, *wh;
    cudaGetSymbolAddress((void**)&h1,  g_h1);
    cudaGetSymbolAddress((void**)&sa,  g_sa);
    cudaGetSymbolAddress((void**)&sh,  g_sh);
    cudaGetSymbolAddress((void**)&ah,  g_ah);
    cudaGetSymbolAddress((void**)&xbh, g_xbh);
    cudaGetSymbolAddress((void**)&ybh, g_ybh);
    cudaGetSymbolAddress((void**)&rl,  g_rl);
    cudaGetSymbolAddress((void**)&il,  g_il);
    cudaGetSymbolAddress((void**)&lh,  g_lh);
    cudaGetSymbolAddress((void**)&zh,  g_zh);
    cudaGetSymbolAddress((void**)&wh,  g_wh);

    cudaFuncSetAttribute(hmma_gemm<0,1,false,false,true>,  cudaFuncAttributeMaxDynamicSharedMemorySize, GEMM_SMEM);
    cudaFuncSetAttribute(hmma_gemm<0,0,false,false,true>,  cudaFuncAttributeMaxDynamicSharedMemorySize, GEMM_SMEM);
    cudaFuncSetAttribute(hmma_gemm<0,0,true,false,false>,  cudaFuncAttributeMaxDynamicSharedMemorySize, GEMM_SMEM);
    cudaFuncSetAttribute(hmma_gemm<0,0,false,true,false>,  cudaFuncAttributeMaxDynamicSharedMemorySize, GEMM_SMEM);

    const dim3 tsb(32, 8);
    const int gCV = (BB * S4 * DD2 + 255) / 256;     // conv: 4 s-positions/thread
    const int gSC2 = (BB * NC * DD2 + 255) / 256;

    const dim3 gemXY(2048 / 128, MM / 256);   // dual Wx|Wy (fp16 out)
    const dim3 gemAI(2048 / 128, MM / 256);   // dual Wa|Wi (fp16 out)
    const dim3 gemGU(8192 / 128, MM / 256);   // interleaved Wg|Wu (gated)
    const dim3 gemO (1024 / 128, MM / 256);   // Wo (K=1024, fp32+res)
    const dim3 gemDn(1024 / 128, MM / 256);   // Wd (K=4096, fp32+res)

    // all weight prep in ONE launch + rmsnorm1
    prep_all_kernel<<<5*1024 + 3*4096, tsb>>>(Wx, Wy, Wa, Wi, Wo, Wg, Wu, Wd, wh);
    rmsnorm_f16_kernel<<<MM, 256>>>(x, norm1_w, ah);
    // xb = t @ Wx ; yb = gelu(t @ Wy)  [dual, fp16 out]
    hmma_gemm<0,1,false,false,true><<<gemXY, 512, GEMM_SMEM>>>(ah, wh + WOFF_X,
        nullptr, nullptr, nullptr, xbh, ybh, nullptr, DD, DD);
    // conv -> ah (fp16)
    conv_f16_kernel<<<gCV, 256>>>((const __half2*)xbh, conv_w, conv_b, (__half2*)ah);
    // rlin -> rl ; ilin -> il  [dual, fp16 out]
    hmma_gemm<0,0,false,false,true><<<gemAI, 512, GEMM_SMEM>>>(ah, wh + WOFF_A,
        nullptr, nullptr, nullptr, rl, il, nullptr, DD, DD);
    // gates + chunked scan + z = h*yb -> ah (fp16)
    scan1_kernel<<<gSC2, 256>>>((__half2*)rl, (const __half2*)il, (const __half2*)ah,
                                lam, (__half2*)lh, (float2*)sa, (float2*)sh);
    scan2_kernel<<<(BB * DD2 + 255) / 256, 256>>>((const float2*)sa, (float2*)sh);
    scan3_kernel<<<gSC2, 256>>>((const __half2*)rl, (const __half2*)lh,
                                (const float2*)sh, (const __half2*)ybh, (__half2*)ah);
    // h1 = x + z @ Wo   (fp32 trunk)
    hmma_gemm<0,0,true,false,false><<<gemO, 512, GEMM_SMEM>>>(ah, wh + WOFF_O,
        x, h1, h1, nullptr, nullptr, nullptr, DD, DD);
    // u = rmsnorm(h1) -> ah
    rmsnorm_f16_kernel<<<MM, 256>>>(h1, norm2_w, ah);
    // ff = gelu(u @ Wg) * (u @ Wu) -> zh  [gated]
    hmma_gemm<0,0,false,true,false><<<gemGU, 512, GEMM_SMEM>>>(ah, wh + WOFF_GU,
        nullptr, nullptr, nullptr, nullptr, nullptr, zh, HH, DD);
    // out = h1 + ff @ Wd
    hmma_gemm<0,0,true,false,false><<<gemDn, 512, GEMM_SMEM>>>(zh, wh + WOFF_D,
        h1, out, out, nullptr, nullptr, nullptr, DD, HH);
}

// round 17
// speedup vs baseline: 1.0384x; 1.0191x over previous
#include <cuda_runtime.h>
#include <cuda_fp16.h>
#include <math.h>
#include <stdint.h>

// Problem dims (fixed by the dataset)
#define BB 4
#define SS 2048
#define DD 1024
#define HH 4096
#define MM (BB*SS)          // 8192 rows
#define NC 32               // scan chunks
#define CL (SS/NC)          // 64 steps per chunk
#define DD2 (DD/2)

// ---------------------------------------------------------------------------
// Scratch (static device globals; no allocation in kernel_launch)
// ---------------------------------------------------------------------------
__device__ __align__(16) float g_h1 [(size_t)MM*DD];    // h1 trunk (fp32)
__device__ __align__(16) float g_sa [(size_t)BB*NC*DD]; // chunk a-products
__device__ __align__(16) float g_sh [(size_t)BB*NC*DD]; // chunk h-carries

// fp16 streams
__device__ __align__(16) __half g_ah [(size_t)MM*DD];  // rmsnorm out / conv out / z
__device__ __align__(16) __half g_xbh[(size_t)MM*DD];  // xb (gemXY C1)
__device__ __align__(16) __half g_ybh[(size_t)MM*DD];  // yb (gemXY C2, gelu)
__device__ __align__(16) __half g_rl [(size_t)MM*DD];  // rlin -> a (in place)
__device__ __align__(16) __half g_il [(size_t)MM*DD];  // ilin
__device__ __align__(16) __half g_lh [(size_t)MM*DD];  // scan local h (fp16)
__device__ __align__(16) __half g_zh [(size_t)MM*HH];  // gated-MLP intermediate
// fp16 transposed weights, packed arena (17M halfs)
#define WOFF_X  ((size_t)0)
#define WOFF_Y  ((size_t)1*1024*1024)   // follows X (dual Wx|Wy)
#define WOFF_A  ((size_t)2*1024*1024)
#define WOFF_I  ((size_t)3*1024*1024)   // follows A (dual Wa|Wi)
#define WOFF_O  ((size_t)4*1024*1024)
#define WOFF_GU ((size_t)5*1024*1024)   // Wg/Wu column-interleaved (8192 rows)
#define WOFF_D  ((size_t)13*1024*1024)
__device__ __align__(16) __half g_wh[(size_t)17*1024*1024];

// ---------------------------------------------------------------------------
// Math helpers
// ---------------------------------------------------------------------------
__device__ __forceinline__ float tanh_approx(float x) {
    float y;
    asm("tanh.approx.f32 %0, %1;" : "=f"(y) : "f"(x));
    return y;
}
__device__ __forceinline__ float geluf(float x) {
    const float c = 0.7978845608028654f; // sqrt(2/pi)
    float x3 = x * x * x;
    float t  = tanh_approx(c * (x + 0.044715f * x3));
    return 0.5f * x * (1.0f + t);
}
__device__ __forceinline__ float sigmoidf(float x) {
    return 1.0f / (1.0f + __expf(-x));
}
__device__ __forceinline__ float softplusf(float x) {
    return fmaxf(x, 0.0f) + log1pf(expf(-fabsf(x)));   // prep-only; keep accurate
}

// ---------------------------------------------------------------------------
// PTX helpers (baseline compute_103 features only)
// ---------------------------------------------------------------------------
__device__ __forceinline__ uint32_t smem_u32(const void* p) {
    uint32_t a;
    asm("{ .reg .u64 t; cvta.to.shared.u64 t, %1; cvt.u32.u64 %0, t; }" : "=r"(a) : "l"(p));
    return a;
}
__device__ __forceinline__ void cp_async16(uint32_t dst, const void* src) {
    asm volatile("cp.async.cg.shared.global [%0], [%1], 16;" :: "r"(dst), "l"(src) : "memory");
}
__device__ __forceinline__ void ldm_x4(uint32_t& r0, uint32_t& r1, uint32_t& r2, uint32_t& r3,
                                       uint32_t addr) {
    asm volatile("ldmatrix.sync.aligned.m8n8.x4.shared.b16 {%0,%1,%2,%3}, [%4];"
                 : "=r"(r0), "=r"(r1), "=r"(r2), "=r"(r3) : "r"(addr));
}
__device__ __forceinline__ void mma16816(float* c, const uint32_t* a, const uint32_t* b) {
    asm volatile(
        "mma.sync.aligned.m16n8k16.row.col.f32.f16.f16.f32 "
        "{%0,%1,%2,%3}, {%4,%5,%6,%7}, {%8,%9}, {%0,%1,%2,%3};"
        : "+f"(c[0]), "+f"(c[1]), "+f"(c[2]), "+f"(c[3])
        : "r"(a[0]), "r"(a[1]), "r"(a[2]), "r"(a[3]), "r"(b[0]), "r"(b[1]));
}

// ---------------------------------------------------------------------------
// Single-product fp16 HMMA GEMM: C = act(A @ W^T) (+R).
// CTA 256x128, BK=64, 16 warps (4Mx4N, warp tile 64x32), 4-stage cp.async,
// fill-distance 3, single __syncthreads per chunk, 1 CTA/SM  (R13 config).
// ---------------------------------------------------------------------------
#define GSTRIDE 144u
#define TILE_A  36864u            // 256 rows * 144B
#define STG_B   55296u            // A(36864) + B(18432)
#define GEMM_SMEM (4*STG_B)       // 221184

template<int ACT1, int ACT2, bool RES, bool GATED, bool OUT16>
__global__ void __launch_bounds__(512, 1)
hmma_gemm(const __half* __restrict__ Ah, const __half* __restrict__ Bh,
          const float* __restrict__ R, float* __restrict__ C1, float* __restrict__ C2,
          __half* __restrict__ H1o, __half* __restrict__ H2o,
          __half* __restrict__ ZH,
          int NH, int K)
{
    extern __shared__ char smem[];
    const uint32_t sb = smem_u32(smem);
    const int tid  = threadIdx.x;
    const int wid  = tid >> 5;
    const int lane = tid & 31;
    const int bm = blockIdx.y * 256;
    const int bn = blockIdx.x * 128;
    const int wr = wid >> 2;          // warp row 0..3 (64 rows each)
    const int wc = wid & 3;           // warp col 0..3 (32 cols each)

    const int nch = K >> 6;           // BK = 64

    auto fill = [&](int ch) {
        const int k0 = ch << 6;
        const uint32_t st = sb + (uint32_t)(ch & 3) * STG_B;
        #pragma unroll
        for (int r = 0; r < 4; r++) {            // A: 2048 16B chunks
            const int c = tid + (r << 9);
            const int row = c >> 3, kc = c & 7;
            const uint32_t dst = (uint32_t)row * GSTRIDE + (uint32_t)(kc << 4);
            cp_async16(st + dst, Ah + (size_t)(bm + row) * K + k0 + (kc << 3));
        }
        #pragma unroll
        for (int r = 0; r < 2; r++) {            // B: 1024 16B chunks
            const int c = tid + (r << 9);
            const int row = c >> 3, kc = c & 7;
            const uint32_t dst = (uint32_t)row * GSTRIDE + (uint32_t)(kc << 4);
            cp_async16(st + TILE_A + dst, Bh + (size_t)(bn + row) * K + k0 + (kc << 3));
        }
        asm volatile("cp.async.commit_group;" ::: "memory");
    };

    float acc[4][4][4];
    #pragma unroll
    for (int i = 0; i < 4; i++)
        #pragma unroll
        for (int j = 0; j < 4; j++)
            #pragma unroll
            for (int q = 0; q < 4; q++) acc[i][j][q] = 0.0f;

    fill(0);
    if (nch > 1) fill(1);
    if (nch > 2) fill(2);

    const int l16  = lane & 15;
    const int ahi  = (lane >> 4) << 4;
    const int brow = ((lane >> 4) << 3) + (lane & 7);
    const int bhi  = ((lane >> 3) & 1) << 4;

    for (int i = 0; i < nch; i++) {
        if      (i + 2 < nch) asm volatile("cp.async.wait_group 2;" ::: "memory");
        else if (i + 1 < nch) asm volatile("cp.async.wait_group 1;" ::: "memory");
        else                  asm volatile("cp.async.wait_group 0;" ::: "memory");
        __syncthreads();   // single barrier per chunk (fill-distance-3, 4 buffers)

        const uint32_t st  = sb + (uint32_t)(i & 3) * STG_B;
        const uint32_t sAh = st;
        const uint32_t sBh = st + TILE_A;

        #pragma unroll
        for (int ks = 0; ks < 4; ks++) {
            uint32_t ah[4][4];
            #pragma unroll
            for (int mt = 0; mt < 4; mt++) {
                const uint32_t ra = (uint32_t)(wr*64 + mt*16 + l16) * GSTRIDE
                                  + (uint32_t)(ks*32 + ahi);
                ldm_x4(ah[mt][0], ah[mt][1], ah[mt][2], ah[mt][3], sAh + ra);
            }
            #pragma unroll
            for (int ntp = 0; ntp < 2; ntp++) {
                uint32_t bq[4];
                const uint32_t rb = (uint32_t)(wc*32 + ntp*16 + brow) * GSTRIDE
                                  + (uint32_t)(ks*32 + bhi);
                ldm_x4(bq[0], bq[1], bq[2], bq[3], sBh + rb);
                #pragma unroll
                for (int mt = 0; mt < 4; mt++) {
                    mma16816(acc[mt][2*ntp],   ah[mt], bq);
                    mma16816(acc[mt][2*ntp+1], ah[mt], bq + 2);
                }
            }
        }
        if (i + 3 < nch) fill(i + 3);
    }

    const int erow = lane >> 2;
    const int ecol = (lane & 3) << 1;

    if constexpr (GATED) {
        #pragma unroll
        for (int mt = 0; mt < 4; mt++) {
            #pragma unroll
            for (int nt = 0; nt < 4; nt++) {
                const int r0 = bm + wr*64 + mt*16 + erow;
                const int j  = ((bn + wc*32 + nt*8 + ecol) >> 1);
                const float f0 = geluf(acc[mt][nt][0]) * acc[mt][nt][1];
                const float f1 = geluf(acc[mt][nt][2]) * acc[mt][nt][3];
                const float f0n = __shfl_down_sync(0xffffffff, f0, 1);
                const float f1n = __shfl_down_sync(0xffffffff, f1, 1);
                if ((lane & 1) == 0) {
                    *(__half2*)(ZH + (size_t)r0     * NH + j) = __floats2half2_rn(f0, f0n);
                    *(__half2*)(ZH + (size_t)(r0+8) * NH + j) = __floats2half2_rn(f1, f1n);
                }
            }
        }
        return;
    }

    if constexpr (OUT16) {
        __half* Hout;
        int act, cb;
        if (bn < NH) { Hout = H1o; act = ACT1; cb = bn; }
        else         { Hout = H2o; act = ACT2; cb = bn - NH; }
        #pragma unroll
        for (int mt = 0; mt < 4; mt++) {
            #pragma unroll
            for (int nt = 0; nt < 4; nt++) {
                const int r0 = bm + wr*64 + mt*16 + erow;
                const int cc = cb + wc*32 + nt*8 + ecol;
                float v0 = acc[mt][nt][0], v1 = acc[mt][nt][1];
                float v2 = acc[mt][nt][2], v3 = acc[mt][nt][3];
                if (act == 1) { v0 = geluf(v0); v1 = geluf(v1); v2 = geluf(v2); v3 = geluf(v3); }
                *(__half2*)(Hout + (size_t)r0     * NH + cc) =
                    __floats2half2_rn(v0, v1);
                *(__half2*)(Hout + (size_t)(r0+8) * NH + cc) =
                    __floats2half2_rn(v2, v3);
            }
        }
        return;
    }

    // fp32 epilogue (with residual)
    float* Cout;
    int act, cb;
    if (bn < NH) { Cout = C1; act = ACT1; cb = bn; }
    else         { Cout = C2; act = ACT2; cb = bn - NH; }

    #pragma unroll
    for (int mt = 0; mt < 4; mt++) {
        #pragma unroll
        for (int nt = 0; nt < 4; nt++) {
            const int r0 = bm + wr*64 + mt*16 + erow;
            const int cc = cb + wc*32 + nt*8 + ecol;
            float v0 = acc[mt][nt][0], v1 = acc[mt][nt][1];
            float v2 = acc[mt][nt][2], v3 = acc[mt][nt][3];
            if (act == 1) { v0 = geluf(v0); v1 = geluf(v1); v2 = geluf(v2); v3 = geluf(v3); }
            if (RES) {
                const float2 ra = *(const float2*)(R + (size_t)r0 * NH + cc);
                const float2 rb = *(const float2*)(R + (size_t)(r0+8) * NH + cc);
                v0 += ra.x; v1 += ra.y; v2 += rb.x; v3 += rb.y;
            }
            *(float2*)(Cout + (size_t)r0     * NH + cc) = make_float2(v0, v1);
            *(float2*)(Cout + (size_t)(r0+8) * NH + cc) = make_float2(v2, v3);
        }
    }
}

// ---------------------------------------------------------------------------
// Weight transpose to fp16 with half2-vectorized stores (fused, one launch).
// ---------------------------------------------------------------------------
__device__ __forceinline__ void tsplit_body(const float* __restrict__ W,
                                            __half* __restrict__ Th,
                                            int Kd, int Nd, int rstride, int roff,
                                            int bx, int by)
{
    __shared__ float tile[32][33];   // [k_local][n_local]
    const int n0 = bx * 32, k0 = by * 32;
    const int tx = threadIdx.x, ty = threadIdx.y;   // (32, 8)
    #pragma unroll
    for (int i = 0; i < 32; i += 8)
        tile[ty + i][tx] = W[(size_t)(k0 + ty + i) * Nd + n0 + tx];
    __syncthreads();
    const int j  = tx & 15;
    const int nn = ty + ((tx >> 4) << 3);
    #pragma unroll
    for (int i = 0; i < 32; i += 16) {
        const float v0 = tile[2*j][nn + i];
        const float v1 = tile[2*j + 1][nn + i];
        const size_t o = ((size_t)(n0 + nn + i) * rstride + roff) * Kd + k0 + 2*j;
        *(__half2*)&Th[o] = __floats2half2_rn(v0, v1);
    }
}

__global__ void prep_all_kernel(const float* __restrict__ Wx, const float* __restrict__ Wy,
                                const float* __restrict__ Wa, const float* __restrict__ Wi,
                                const float* __restrict__ Wo, const float* __restrict__ Wg,
                                const float* __restrict__ Wu, const float* __restrict__ Wd,
                                __half* __restrict__ wh)
{
    int b = blockIdx.x;
    if (b < 5 * 1024) {
        const int w = b >> 10;
        const int t = b & 1023;
        const float* W;
        size_t off;
        switch (w) {
            case 0:  W = Wx; off = WOFF_X; break;
            case 1:  W = Wy; off = WOFF_Y; break;
            case 2:  W = Wa; off = WOFF_A; break;
            case 3:  W = Wi; off = WOFF_I; break;
            default: W = Wo; off = WOFF_O; break;
        }
        tsplit_body(W, wh + off, DD, DD, 1, 0, t & 31, t >> 5);
        return;
    }
    b -= 5 * 1024;
    if (b < 4096) {        // Wg: even interleaved rows
        tsplit_body(Wg, wh + WOFF_GU, DD, HH, 2, 0, b & 127, b >> 7);
        return;
    }
    b -= 4096;
    if (b < 4096) {        // Wu: odd interleaved rows
        tsplit_body(Wu, wh + WOFF_GU, DD, HH, 2, 1, b & 127, b >> 7);
        return;
    }
    b -= 4096;             // Wd
    tsplit_body(Wd, wh + WOFF_D, HH, DD, 1, 0, b & 31, b >> 5);
}

// ---------------------------------------------------------------------------
// RMSNorm with fp16 output (float2 / half2 vectorized; D=1024, 256 threads)
// ---------------------------------------------------------------------------
__global__ void rmsnorm_f16_kernel(const float* __restrict__ x,
                                   const float* __restrict__ w,
                                   __half* __restrict__ oh)
{
    const int row = blockIdx.x;
    const float2* xr = (const float2*)(x + (size_t)row * DD);
    const float2* w2 = (const float2*)w;
    float ss = 0.0f;
    float2 v[2];
    #pragma unroll
    for (int r = 0; r < 2; r++) {
        v[r] = xr[threadIdx.x + r * 256];
        ss = fmaf(v[r].x, v[r].x, fmaf(v[r].y, v[r].y, ss));
    }
    #pragma unroll
    for (int off = 16; off > 0; off >>= 1)
        ss += __shfl_xor_sync(0xffffffff, ss, off);
    __shared__ float red[8];
    const int lane = threadIdx.x & 31, wid = threadIdx.x >> 5;
    if (lane == 0) red[wid] = ss;
    __syncthreads();
    if (wid == 0) {
        float s = (lane < 8) ? red[lane] : 0.0f;
        #pragma unroll
        for (int off = 4; off > 0; off >>= 1)
            s += __shfl_xor_sync(0xffffffff, s, off);
        if (lane == 0) red[0] = s;
    }
    __syncthreads();
    const float inv = rsqrtf(red[0] / (float)DD + 1e-6f);
    __half2* o2 = (__half2*)(oh + (size_t)row * DD);
    #pragma unroll
    for (int r = 0; r < 2; r++) {
        const float2 ww = w2[threadIdx.x + r * 256];
        o2[threadIdx.x + r * 256] =
            __floats2half2_rn(v[r].x * inv * ww.x, v[r].y * inv * ww.y);
    }
}

// ---------------------------------------------------------------------------
// Causal depthwise conv (K=4), half2 vectorized, 4 sequence positions/thread.
// ---------------------------------------------------------------------------
#define S4 (SS/4)
__global__ void conv_f16_kernel(const __half2* __restrict__ in,
                                const float* __restrict__ cw,
                                const float* __restrict__ cb,
                                __half2* __restrict__ oh)
{
    const int idx = blockIdx.x * blockDim.x + threadIdx.x;
    if (idx >= BB * S4 * DD2) return;
    const int d2    = idx % DD2;
    const int s4    = (idx / DD2) % S4;
    const int batch = idx / (DD2 * S4);
    const int s0    = s4 * 4;
    const size_t base = ((size_t)batch * SS + s0) * DD2 + d2;

    float2 v[7];
    if (s0 >= 3) {
        #pragma unroll
        for (int i = 0; i < 7; i++)
            v[i] = __half22float2(in[base + (size_t)(i - 3) * DD2]);
    } else {
        #pragma unroll
        for (int i = 0; i < 7; i++)
            v[i] = (s0 + i - 3 >= 0)
                 ? __half22float2(in[base + (size_t)(i - 3) * DD2])
                 : make_float2(0.0f, 0.0f);
    }
    float w0[4], w1[4];
    #pragma unroll
    for (int k = 0; k < 4; k++) {
        w0[k] = cw[k * DD + 2*d2];
        w1[k] = cw[k * DD + 2*d2 + 1];
    }
    const float b0 = cb[2*d2], b1 = cb[2*d2 + 1];

    #pragma unroll
    for (int j = 0; j < 4; j++) {
        float a0 = b0, a1 = b1;
        #pragma unroll
        for (int k = 0; k < 4; k++) {
            a0 = fmaf(w0[k], v[j + k].x, a0);
            a1 = fmaf(w1[k], v[j + k].y, a1);
        }
        oh[base + (size_t)j * DD2] = __floats2half2_rn(a0, a1);
    }
}

// ---------------------------------------------------------------------------
// Scan pass 1 (half2): gates + chunk-local scan (MUFU exp path).
// ---------------------------------------------------------------------------
__global__ void scan1_kernel(__half2* __restrict__ rlin_a,
                             const __half2* __restrict__ ilin,
                             const __half2* __restrict__ xc,
                             const float* __restrict__ lam,
                             __half2* __restrict__ lh,
                             float2* __restrict__ sa,
                             float2* __restrict__ sh)
{
    const int idx = blockIdx.x * blockDim.x + threadIdx.x;
    if (idx >= BB * NC * DD2) return;
    const int d2    = idx % DD2;
    const int chunk = (idx / DD2) % NC;
    const int batch = idx / (DD2 * NC);
    const float cf0 = -8.0f * softplusf(lam[2*d2]);
    const float cf1 = -8.0f * softplusf(lam[2*d2 + 1]);
    const size_t base = ((size_t)batch * SS + (size_t)chunk * CL) * DD2 + d2;

    float p0 = 1.0f, p1 = 1.0f, h0 = 0.0f, h1 = 0.0f;
    for (int t = 0; t < CL; t++) {
        const size_t off = base + (size_t)t * DD2;
        const float2 rv = __half22float2(rlin_a[off]);
        const float2 iv = __half22float2(ilin[off]);
        const float2 xv = __half22float2(xc[off]);
        const float a0 = __expf(cf0 * sigmoidf(rv.x));
        const float a1 = __expf(cf1 * sigmoidf(rv.y));
        const float b0 = sqrtf(fmaxf(1.0f - a0*a0, 1e-12f)) * sigmoidf(iv.x) * xv.x;
        const float b1 = sqrtf(fmaxf(1.0f - a1*a1, 1e-12f)) * sigmoidf(iv.y) * xv.y;
        h0 = fmaf(a0, h0, b0);
        h1 = fmaf(a1, h1, b1);
        p0 *= a0; p1 *= a1;
        rlin_a[off] = __floats2half2_rn(a0, a1);
        lh[off]     = __floats2half2_rn(h0, h1);
    }
    sa[idx] = make_float2(p0, p1);
    sh[idx] = make_float2(h0, h1);
}

// ---------------------------------------------------------------------------
// Scan pass 2 (float2): combine chunk carries.
// ---------------------------------------------------------------------------
__global__ void scan2_kernel(const float2* __restrict__ sa, float2* __restrict__ sh)
{
    const int idx = blockIdx.x * blockDim.x + threadIdx.x;
    if (idx >= BB * DD2) return;
    const int d2 = idx % DD2, batch = idx / DD2;
    float H0 = 0.0f, H1 = 0.0f;
    for (int c = 0; c < NC; c++) {
        const size_t o = ((size_t)batch * NC + c) * DD2 + d2;
        const float2 av = sa[o];
        const float2 hv = sh[o];
        H0 = fmaf(av.x, H0, hv.x);
        H1 = fmaf(av.y, H1, hv.y);
        sh[o] = make_float2(H0, H1);
    }
}

// ---------------------------------------------------------------------------
// Scan pass 3 (half2): apply carries, z = h * yb, fp16 out.
// ---------------------------------------------------------------------------
__global__ void scan3_kernel(const __half2* __restrict__ aArr,
                             const __half2* __restrict__ lhArr,
                             const float2* __restrict__ sh,
                             const __half2* __restrict__ yb,
                             __half2* __restrict__ zh)
{
    const int idx = blockIdx.x * blockDim.x + threadIdx.x;
    if (idx >= BB * NC * DD2) return;
    const int d2    = idx % DD2;
    const int chunk = (idx / DD2) % NC;
    const int batch = idx / (DD2 * NC);
    float c0 = 0.0f, c1 = 0.0f;
    if (chunk != 0) {
        const float2 cv = sh[((size_t)batch * NC + chunk - 1) * DD2 + d2];
        c0 = cv.x; c1 = cv.y;
    }
    const size_t base = ((size_t)batch * SS + (size_t)chunk * CL) * DD2 + d2;

    float p0 = 1.0f, p1 = 1.0f;
    for (int t = 0; t < CL; t++) {
        const size_t off = base + (size_t)t * DD2;
        const float2 av = __half22float2(aArr[off]);
        const float2 lv = __half22float2(lhArr[off]);
        const float2 yv = __half22float2(yb[off]);
        p0 *= av.x; p1 *= av.y;
        const float z0 = fmaf(p0, c0, lv.x) * yv.x;
        const float z1 = fmaf(p1, c1, lv.y) * yv.y;
        zh[off] = __floats2half2_rn(z0, z1);
    }
}

// ---------------------------------------------------------------------------
// Launch
// ---------------------------------------------------------------------------
extern "C" void kernel_launch(void* const* d_in, const int* in_sizes, int n_in,
                              void* d_out, int out_size)
{
    const float* x       = (const float*)d_in[0];
    const float* norm1_w = (const float*)d_in[1];
    const float* Wx      = (const float*)d_in[2];
    const float* Wy      = (const float*)d_in[3];
    const float* conv_w  = (const float*)d_in[4];
    const float* conv_b  = (const float*)d_in[5];
    const float* Wi      = (const float*)d_in[6];
    const float* Wa      = (const float*)d_in[7];
    const float* lam     = (const float*)d_in[8];
    const float* Wo      = (const float*)d_in[9];
    const float* norm2_w = (const float*)d_in[10];
    const float* Wg      = (const float*)d_in[11];
    const float* Wu      = (const float*)d_in[12];
    const float* Wd      = (const float*)d_in[13];
    float* out = (float*)d_out;

    float *h1, *sa, *sh;
    __half *ah, *xbh, *ybh, *rl, *il, *lh, *zh, *wh;
    cudaGetSymbolAddress((void**)&h1,  g_h1);
    cudaGetSymbolAddress((void**)&sa,  g_sa);
    cudaGetSymbolAddress((void**)&sh,  g_sh);
    cudaGetSymbolAddress((void**)&ah,  g_ah);
    cudaGetSymbolAddress((void**)&xbh, g_xbh);
    cudaGetSymbolAddress((void**)&ybh, g_ybh);
    cudaGetSymbolAddress((void**)&rl,  g_rl);
    cudaGetSymbolAddress((void**)&il,  g_il);
    cudaGetSymbolAddress((void**)&lh,  g_lh);
    cudaGetSymbolAddress((void**)&zh,  g_zh);
    cudaGetSymbolAddress((void**)&wh,  g_wh);

    cudaFuncSetAttribute(hmma_gemm<0,1,false,false,true>,  cudaFuncAttributeMaxDynamicSharedMemorySize, GEMM_SMEM);
    cudaFuncSetAttribute(hmma_gemm<0,0,false,false,true>,  cudaFuncAttributeMaxDynamicSharedMemorySize, GEMM_SMEM);
    cudaFuncSetAttribute(hmma_gemm<0,0,true,false,false>,  cudaFuncAttributeMaxDynamicSharedMemorySize, GEMM_SMEM);
    cudaFuncSetAttribute(hmma_gemm<0,0,false,true,false>,  cudaFuncAttributeMaxDynamicSharedMemorySize, GEMM_SMEM);

    const dim3 tsb(32, 8);
    const int gCV = (BB * S4 * DD2 + 255) / 256;     // conv: 4 s-positions/thread
    const int gSC2 = (BB * NC * DD2 + 255) / 256;

    const dim3 gemXY(2048 / 128, MM / 256);   // dual Wx|Wy (fp16 out)
    const dim3 gemAI(2048 / 128, MM / 256);   // dual Wa|Wi (fp16 out)
    const dim3 gemGU(8192 / 128, MM / 256);   // interleaved Wg|Wu (gated)
    const dim3 gemO (1024 / 128, MM / 256);   // Wo (K=1024, fp32+res)
    const dim3 gemDn(1024 / 128, MM / 256);   // Wd (K=4096, fp32+res)

    // all weight prep in ONE launch + rmsnorm1
    prep_all_kernel<<<5*1024 + 3*4096, tsb>>>(Wx, Wy, Wa, Wi, Wo, Wg, Wu, Wd, wh);
    rmsnorm_f16_kernel<<<MM, 256>>>(x, norm1_w, ah);
    // xb = t @ Wx ; yb = gelu(t @ Wy)  [dual, fp16 out]
    hmma_gemm<0,1,false,false,true><<<gemXY, 512, GEMM_SMEM>>>(ah, wh + WOFF_X,
        nullptr, nullptr, nullptr, xbh, ybh, nullptr, DD, DD);
    // conv -> ah (fp16)
    conv_f16_kernel<<<gCV, 256>>>((const __half2*)xbh, conv_w, conv_b, (__half2*)ah);
    // rlin -> rl ; ilin -> il  [dual, fp16 out]
    hmma_gemm<0,0,false,false,true><<<gemAI, 512, GEMM_SMEM>>>(ah, wh + WOFF_A,
        nullptr, nullptr, nullptr, rl, il, nullptr, DD, DD);
    // gates + chunked scan + z = h*yb -> ah (fp16)
    scan1_kernel<<<gSC2, 256>>>((__half2*)rl, (const __half2*)il, (const __half2*)ah,
                                lam, (__half2*)lh, (float2*)sa, (float2*)sh);
    scan2_kernel<<<(BB * DD2 + 255) / 256, 256>>>((const float2*)sa, (float2*)sh);
    scan3_kernel<<<gSC2, 256>>>((const __half2*)rl, (const __half2*)lh,
                                (const float2*)sh, (const __half2*)ybh, (__half2*)ah);
    // h1 = x + z @ Wo   (fp32 trunk)
    hmma_gemm<0,0,true,false,false><<<gemO, 512, GEMM_SMEM>>>(ah, wh + WOFF_O,
        x, h1, h1, nullptr, nullptr, nullptr, DD, DD);
    // u = rmsnorm(h1) -> ah
    rmsnorm_f16_kernel<<<MM, 256>>>(h1, norm2_w, ah);
    // ff = gelu(u @ Wg) * (u @ Wu) -> zh  [gated]
    hmma_gemm<0,0,false,true,false><<<gemGU, 512, GEMM_SMEM>>>(ah, wh + WOFF_GU,
        nullptr, nullptr, nullptr, nullptr, nullptr, zh, HH, DD);
    // out = h1 + ff @ Wd
    hmma_gemm<0,0,true,false,false><<<gemDn, 512, GEMM_SMEM>>>(zh, wh + WOFF_D,
        h1, out, out, nullptr, nullptr, nullptr, DD, HH);
}